// round 1
// baseline (speedup 1.0000x reference)
#include <cuda_runtime.h>
#include <cuda_bf16.h>
#include <cstdint>

// Problem constants
#define NODES_MAX 50000
#define H 256
#define D_IN 518
#define D_OUT 128

// ---------------- device scratch (no cudaMalloc allowed) ----------------
__device__ float g_h  [NODES_MAX * H];
__device__ float g_hw [NODES_MAX * H];
__device__ float g_agg[NODES_MAX * H];
__device__ float g_dis[NODES_MAX];
__device__ int   g_deg[NODES_MAX];
__device__ float g_mean[H];

// ---------------- degree / normalization ----------------
__global__ void deg_kernel(const int* __restrict__ dst, int* __restrict__ deg, int E) {
    int i = blockIdx.x * blockDim.x + threadIdx.x;
    if (i < E) atomicAdd(&deg[dst[i]], 1);
}

__global__ void dis_kernel(const int* __restrict__ deg, float* __restrict__ dis, int n) {
    int i = blockIdx.x * blockDim.x + threadIdx.x;
    if (i < n) dis[i] = rsqrtf(1.0f + (float)deg[i]);
}

// ---------------- SGEMM: C[N,M] = A[N,K] @ B[K,M] (+bias)(+relu) ----------------
// BM=128, BN=128, BK=8, TM=8, TN=8, 256 threads
__global__ __launch_bounds__(256)
void sgemm_kernel(const float* __restrict__ A, const float* __restrict__ B,
                  const float* __restrict__ bias, float* __restrict__ C,
                  int N, int K, int M, int doRelu)
{
    const int BM = 128, BN = 128, BK = 8, TM = 8, TN = 8;
    __shared__ float As[BK][BM];
    __shared__ float Bs[BK][BN];

    int blockRow = blockIdx.y;
    int blockCol = blockIdx.x;
    int tid = threadIdx.x;

    int threadRow = tid / (BN / TN);   // 0..15
    int threadCol = tid % (BN / TN);   // 0..15

    int innerRowA = tid / 2;           // 0..127
    int innerColA = (tid % 2) * 4;     // 0 or 4
    int innerRowB = tid / 32;          // 0..7
    int innerColB = (tid % 32) * 4;    // 0..124

    float acc[TM][TN];
#pragma unroll
    for (int i = 0; i < TM; i++)
#pragma unroll
        for (int j = 0; j < TN; j++) acc[i][j] = 0.0f;

    int aRow = blockRow * BM + innerRowA;
    const float* Aptr = A + (size_t)aRow * K;
    const float* Bbase = B + (size_t)blockCol * BN + innerColB;

    int numTiles = (K + BK - 1) / BK;
    for (int t = 0; t < numTiles; ++t) {
        int k0 = t * BK;
        // load A tile (scalar: K=518 rows are not 16B aligned)
#pragma unroll
        for (int i = 0; i < 4; ++i) {
            int k = k0 + innerColA + i;
            float v = 0.0f;
            if (aRow < N && k < K) v = Aptr[k];
            As[innerColA + i][innerRowA] = v;
        }
        // load B tile (float4, M=256 aligned)
        {
            int k = k0 + innerRowB;
            float4 v = make_float4(0.f, 0.f, 0.f, 0.f);
            if (k < K) v = *reinterpret_cast<const float4*>(Bbase + (size_t)k * M);
            Bs[innerRowB][innerColB + 0] = v.x;
            Bs[innerRowB][innerColB + 1] = v.y;
            Bs[innerRowB][innerColB + 2] = v.z;
            Bs[innerRowB][innerColB + 3] = v.w;
        }
        __syncthreads();

#pragma unroll
        for (int kk = 0; kk < BK; ++kk) {
            float regA[TM], regB[TN];
#pragma unroll
            for (int i = 0; i < TM; i++) regA[i] = As[kk][threadRow * TM + i];
#pragma unroll
            for (int j = 0; j < TN; j++) regB[j] = Bs[kk][threadCol * TN + j];
#pragma unroll
            for (int i = 0; i < TM; i++)
#pragma unroll
                for (int j = 0; j < TN; j++)
                    acc[i][j] = fmaf(regA[i], regB[j], acc[i][j]);
        }
        __syncthreads();
    }

    // epilogue
#pragma unroll
    for (int i = 0; i < TM; i++) {
        int row = blockRow * BM + threadRow * TM + i;
        if (row >= N) continue;
#pragma unroll
        for (int j = 0; j < TN; j++) {
            int col = blockCol * BN + threadCol * TN + j;
            float v = acc[i][j];
            if (bias) v += bias[col];
            if (doRelu) v = fmaxf(v, 0.0f);
            C[(size_t)row * M + col] = v;
        }
    }
}

// ---------------- GCN combine: agg = hw * dis^2 + b ----------------
__global__ void combine_init_kernel(const float* __restrict__ hw,
                                    const float* __restrict__ dis,
                                    const float* __restrict__ b,
                                    float* __restrict__ agg, int n)
{
    int idx = blockIdx.x * blockDim.x + threadIdx.x;   // one float4 chunk
    int row = idx >> 6;                                 // 64 chunks per row (H=256)
    if (row >= n) return;
    int c = (idx & 63) * 4;
    float sn = dis[row] * dis[row];
    float4 v = *reinterpret_cast<const float4*>(hw + (size_t)row * H + c);
    float4 bb = *reinterpret_cast<const float4*>(b + c);
    float4 o;
    o.x = fmaf(v.x, sn, bb.x);
    o.y = fmaf(v.y, sn, bb.y);
    o.z = fmaf(v.z, sn, bb.z);
    o.w = fmaf(v.w, sn, bb.w);
    *reinterpret_cast<float4*>(agg + (size_t)row * H + c) = o;
}

// ---------------- edge scatter: agg[dst] += hw[src] * dis[src]*dis[dst] ----------------
__global__ void scatter_kernel(const int* __restrict__ src, const int* __restrict__ dst,
                               const float* __restrict__ dis,
                               const float* __restrict__ hw, float* __restrict__ agg,
                               int E)
{
    long long idx = (long long)blockIdx.x * blockDim.x + threadIdx.x;
    int e = (int)(idx >> 6);           // 64 float4 chunks per edge
    if (e >= E) return;
    int c = ((int)idx & 63) * 4;
    int s = src[e], d = dst[e];
    float w = dis[s] * dis[d];
    float4 v = *reinterpret_cast<const float4*>(hw + (size_t)s * H + c);
    float* out = agg + (size_t)d * H + c;
    atomicAdd(out + 0, v.x * w);
    atomicAdd(out + 1, v.y * w);
    atomicAdd(out + 2, v.z * w);
    atomicAdd(out + 3, v.w * w);
}

// ---------------- relu copy: h = max(agg, 0) ----------------
__global__ void relu_kernel(const float* __restrict__ in, float* __restrict__ out, int n4) {
    int idx = blockIdx.x * blockDim.x + threadIdx.x;
    if (idx >= n4) return;
    float4 v = reinterpret_cast<const float4*>(in)[idx];
    v.x = fmaxf(v.x, 0.f); v.y = fmaxf(v.y, 0.f);
    v.z = fmaxf(v.z, 0.f); v.w = fmaxf(v.w, 0.f);
    reinterpret_cast<float4*>(out)[idx] = v;
}

// ---------------- mean over nodes ----------------
__global__ void mean_kernel(const float* __restrict__ h, float* __restrict__ mean, int n) {
    float acc = 0.0f;
    for (int r = blockIdx.x; r < n; r += gridDim.x)
        acc += h[(size_t)r * H + threadIdx.x];
    atomicAdd(&mean[threadIdx.x], acc);
}

// ---------------- head MLP: out = relu(g@W1+b1)@W2+b2 ----------------
__global__ void head_kernel(const float* __restrict__ mean,
                            const float* __restrict__ W1, const float* __restrict__ b1,
                            const float* __restrict__ W2, const float* __restrict__ b2,
                            float* __restrict__ out, float invN)
{
    __shared__ float g[H];
    __shared__ float t[D_OUT];
    int tid = threadIdx.x;  // 128 threads
    g[tid]       = mean[tid]       * invN;
    g[tid + 128] = mean[tid + 128] * invN;
    __syncthreads();
    float acc = b1[tid];
    for (int k = 0; k < H; k++) acc = fmaf(g[k], W1[k * D_OUT + tid], acc);
    t[tid] = fmaxf(acc, 0.0f);
    __syncthreads();
    float acc2 = b2[tid];
    for (int k = 0; k < D_OUT; k++) acc2 = fmaf(t[k], W2[k * D_OUT + tid], acc2);
    out[tid] = acc2;
}

// ---------------- launch ----------------
extern "C" void kernel_launch(void* const* d_in, const int* in_sizes, int n_in,
                              void* d_out, int out_size)
{
    const float* x       = (const float*)d_in[0];
    const int*   eidx    = (const int*)  d_in[1];
    // d_in[2] edge_attr, d_in[7] emb_table: unused downstream
    const float* W_enc1  = (const float*)d_in[3];
    const float* b_enc1  = (const float*)d_in[4];
    const float* W_enc2  = (const float*)d_in[5];
    const float* b_enc2  = (const float*)d_in[6];
    const float* W_g[3]  = { (const float*)d_in[8],  (const float*)d_in[10], (const float*)d_in[12] };
    const float* b_g[3]  = { (const float*)d_in[9],  (const float*)d_in[11], (const float*)d_in[13] };
    const float* W_h1    = (const float*)d_in[14];
    const float* b_h1    = (const float*)d_in[15];
    const float* W_h2    = (const float*)d_in[16];
    const float* b_h2    = (const float*)d_in[17];

    const int n = in_sizes[0] / D_IN;       // 50000
    const int E = in_sizes[2];              // 1600000
    const int* src = eidx;
    const int* dst = eidx + E;

    float *p_h, *p_hw, *p_agg, *p_dis, *p_mean;
    int* p_deg;
    cudaGetSymbolAddress((void**)&p_h,    g_h);
    cudaGetSymbolAddress((void**)&p_hw,   g_hw);
    cudaGetSymbolAddress((void**)&p_agg,  g_agg);
    cudaGetSymbolAddress((void**)&p_dis,  g_dis);
    cudaGetSymbolAddress((void**)&p_deg,  g_deg);
    cudaGetSymbolAddress((void**)&p_mean, g_mean);

    // 1) degrees + symmetric norm
    cudaMemsetAsync(p_deg, 0, n * sizeof(int), 0);
    deg_kernel<<<(E + 255) / 256, 256>>>(dst, p_deg, E);
    dis_kernel<<<(n + 255) / 256, 256>>>(p_deg, p_dis, n);

    dim3 gemmBlock(256);
    dim3 gemmGrid(H / 128, (n + 127) / 128);

    // 2) encoder: h = relu(x@W1+b1)@W2+b2
    sgemm_kernel<<<gemmGrid, gemmBlock>>>(x,    W_enc1, b_enc1, p_hw, n, D_IN, H, 1);
    sgemm_kernel<<<gemmGrid, gemmBlock>>>(p_hw, W_enc2, b_enc2, p_h,  n, H,    H, 0);

    // 3) three GCN layers
    const int combineThreads = n * (H / 4);
    const long long scatterThreads = (long long)E * (H / 4);
    const int scatterBlocks = (int)((scatterThreads + 255) / 256);
    for (int l = 0; l < 3; ++l) {
        sgemm_kernel<<<gemmGrid, gemmBlock>>>(p_h, W_g[l], nullptr, p_hw, n, H, H, 0);
        combine_init_kernel<<<(combineThreads + 255) / 256, 256>>>(p_hw, p_dis, b_g[l], p_agg, n);
        scatter_kernel<<<scatterBlocks, 256>>>(src, dst, p_dis, p_hw, p_agg, E);
        relu_kernel<<<(n * H / 4 + 255) / 256, 256>>>(p_agg, p_h, n * H / 4);
    }

    // 4) mean pooling + head
    cudaMemsetAsync(p_mean, 0, H * sizeof(float), 0);
    mean_kernel<<<128, H>>>(p_h, p_mean, n);
    head_kernel<<<1, D_OUT>>>(p_mean, W_h1, b_h1, W_h2, b_h2, (float*)d_out, 1.0f / (float)n);
}

// round 2
// speedup vs baseline: 2.2600x; 2.2600x over previous
#include <cuda_runtime.h>
#include <cuda_bf16.h>
#include <cstdint>

// Problem constants
#define NODES_MAX 50000
#define EDGES_MAX 1600000
#define H 256
#define D_IN 518
#define D_OUT 128

// ---------------- device scratch (no cudaMalloc allowed) ----------------
__device__ float g_h  [NODES_MAX * H];
__device__ float g_hw [NODES_MAX * H];
__device__ float g_dis[NODES_MAX];
__device__ int   g_deg[NODES_MAX];
__device__ int   g_start[NODES_MAX + 1];
__device__ int   g_cursor[NODES_MAX];
__device__ int   g_csr_src[EDGES_MAX];
__device__ float g_mean[H];

// ---------------- degree / normalization ----------------
__global__ void deg_kernel(const int* __restrict__ dst, int* __restrict__ deg, int E) {
    int i = blockIdx.x * blockDim.x + threadIdx.x;
    if (i < E) atomicAdd(&deg[dst[i]], 1);
}

__global__ void dis_kernel(const int* __restrict__ deg, float* __restrict__ dis, int n) {
    int i = blockIdx.x * blockDim.x + threadIdx.x;
    if (i < n) dis[i] = rsqrtf(1.0f + (float)deg[i]);
}

// ---------------- exclusive scan of deg -> start (single block, chunked) ----------------
__global__ void scan_kernel(const int* __restrict__ deg, int* __restrict__ start,
                            int* __restrict__ cursor, int n)
{
    __shared__ int smem[1024];
    __shared__ int carry;
    if (threadIdx.x == 0) { carry = 0; start[0] = 0; }
    __syncthreads();
    for (int base = 0; base < n; base += 1024) {
        int i = base + threadIdx.x;
        int v = (i < n) ? deg[i] : 0;
        smem[threadIdx.x] = v;
        __syncthreads();
#pragma unroll
        for (int off = 1; off < 1024; off <<= 1) {
            int t = (threadIdx.x >= off) ? smem[threadIdx.x - off] : 0;
            __syncthreads();
            smem[threadIdx.x] += t;
            __syncthreads();
        }
        if (i < n) {
            int inc = carry + smem[threadIdx.x];     // inclusive prefix
            start[i + 1] = inc;
            cursor[i] = inc - v;                      // exclusive prefix
        }
        __syncthreads();
        if (threadIdx.x == 1023) carry += smem[1023];
        __syncthreads();
    }
}

// ---------------- bucket edges by dst ----------------
__global__ void fill_csr_kernel(const int* __restrict__ src, const int* __restrict__ dst,
                                int* __restrict__ cursor, int* __restrict__ csr_src, int E)
{
    int e = blockIdx.x * blockDim.x + threadIdx.x;
    if (e < E) {
        int d = dst[e];
        int p = atomicAdd(&cursor[d], 1);
        csr_src[p] = src[e];
    }
}

// ---------------- SGEMM: C[N,M] = A[N,K] @ B[K,M] (+bias)(+relu) ----------------
__global__ __launch_bounds__(256)
void sgemm_kernel(const float* __restrict__ A, const float* __restrict__ B,
                  const float* __restrict__ bias, float* __restrict__ C,
                  int N, int K, int M, int doRelu)
{
    const int BM = 128, BN = 128, BK = 8, TM = 8, TN = 8;
    __shared__ float As[BK][BM];
    __shared__ float Bs[BK][BN];

    int blockRow = blockIdx.y;
    int blockCol = blockIdx.x;
    int tid = threadIdx.x;

    int threadRow = tid / (BN / TN);
    int threadCol = tid % (BN / TN);

    int innerRowA = tid / 2;
    int innerColA = (tid % 2) * 4;
    int innerRowB = tid / 32;
    int innerColB = (tid % 32) * 4;

    float acc[TM][TN];
#pragma unroll
    for (int i = 0; i < TM; i++)
#pragma unroll
        for (int j = 0; j < TN; j++) acc[i][j] = 0.0f;

    int aRow = blockRow * BM + innerRowA;
    const float* Aptr = A + (size_t)aRow * K;
    const float* Bbase = B + (size_t)blockCol * BN + innerColB;

    int numTiles = (K + BK - 1) / BK;
    for (int t = 0; t < numTiles; ++t) {
        int k0 = t * BK;
#pragma unroll
        for (int i = 0; i < 4; ++i) {
            int k = k0 + innerColA + i;
            float v = 0.0f;
            if (aRow < N && k < K) v = Aptr[k];
            As[innerColA + i][innerRowA] = v;
        }
        {
            int k = k0 + innerRowB;
            float4 v = make_float4(0.f, 0.f, 0.f, 0.f);
            if (k < K) v = *reinterpret_cast<const float4*>(Bbase + (size_t)k * M);
            Bs[innerRowB][innerColB + 0] = v.x;
            Bs[innerRowB][innerColB + 1] = v.y;
            Bs[innerRowB][innerColB + 2] = v.z;
            Bs[innerRowB][innerColB + 3] = v.w;
        }
        __syncthreads();

#pragma unroll
        for (int kk = 0; kk < BK; ++kk) {
            float regA[TM], regB[TN];
#pragma unroll
            for (int i = 0; i < TM; i++) regA[i] = As[kk][threadRow * TM + i];
#pragma unroll
            for (int j = 0; j < TN; j++) regB[j] = Bs[kk][threadCol * TN + j];
#pragma unroll
            for (int i = 0; i < TM; i++)
#pragma unroll
                for (int j = 0; j < TN; j++)
                    acc[i][j] = fmaf(regA[i], regB[j], acc[i][j]);
        }
        __syncthreads();
    }

#pragma unroll
    for (int i = 0; i < TM; i++) {
        int row = blockRow * BM + threadRow * TM + i;
        if (row >= N) continue;
#pragma unroll
        for (int j = 0; j < TN; j++) {
            int col = blockCol * BN + threadCol * TN + j;
            float v = acc[i][j];
            if (bias) v += bias[col];
            if (doRelu) v = fmaxf(v, 0.0f);
            C[(size_t)row * M + col] = v;
        }
    }
}

// ---------------- fused GCN aggregation (gather form) ----------------
// h_out[d] = relu( hw[d]*dis[d]^2 + b + sum_{s in N(d)} hw[s]*dis[s]*dis[d] )
// one warp per node; lane handles 8 contiguous floats (2 float4)
__global__ __launch_bounds__(256)
void gather_kernel(const float* __restrict__ hw, const float* __restrict__ dis,
                   const float* __restrict__ b,
                   const int* __restrict__ start, const int* __restrict__ csr_src,
                   float* __restrict__ hout, int n)
{
    int warp = (blockIdx.x * blockDim.x + threadIdx.x) >> 5;
    if (warp >= n) return;
    int lane = threadIdx.x & 31;
    int node = warp;

    float dd = dis[node];
    float self = dd * dd;

    const float4* hrow = reinterpret_cast<const float4*>(hw + (size_t)node * H);
    const float4* bb   = reinterpret_cast<const float4*>(b);
    float4 v0 = hrow[lane * 2 + 0];
    float4 v1 = hrow[lane * 2 + 1];
    float4 b0 = bb[lane * 2 + 0];
    float4 b1 = bb[lane * 2 + 1];

    float4 a0, a1;
    a0.x = fmaf(v0.x, self, b0.x); a0.y = fmaf(v0.y, self, b0.y);
    a0.z = fmaf(v0.z, self, b0.z); a0.w = fmaf(v0.w, self, b0.w);
    a1.x = fmaf(v1.x, self, b1.x); a1.y = fmaf(v1.y, self, b1.y);
    a1.z = fmaf(v1.z, self, b1.z); a1.w = fmaf(v1.w, self, b1.w);

    int j0 = start[node], j1 = start[node + 1];

    int j = j0;
    // unroll by 2 for memory-level parallelism
    for (; j + 2 <= j1; j += 2) {
        int sA = csr_src[j];
        int sB = csr_src[j + 1];
        float wA = dis[sA] * dd;
        float wB = dis[sB] * dd;
        const float4* rA = reinterpret_cast<const float4*>(hw + (size_t)sA * H);
        const float4* rB = reinterpret_cast<const float4*>(hw + (size_t)sB * H);
        float4 uA0 = rA[lane * 2 + 0], uA1 = rA[lane * 2 + 1];
        float4 uB0 = rB[lane * 2 + 0], uB1 = rB[lane * 2 + 1];
        a0.x = fmaf(uA0.x, wA, a0.x); a0.y = fmaf(uA0.y, wA, a0.y);
        a0.z = fmaf(uA0.z, wA, a0.z); a0.w = fmaf(uA0.w, wA, a0.w);
        a1.x = fmaf(uA1.x, wA, a1.x); a1.y = fmaf(uA1.y, wA, a1.y);
        a1.z = fmaf(uA1.z, wA, a1.z); a1.w = fmaf(uA1.w, wA, a1.w);
        a0.x = fmaf(uB0.x, wB, a0.x); a0.y = fmaf(uB0.y, wB, a0.y);
        a0.z = fmaf(uB0.z, wB, a0.z); a0.w = fmaf(uB0.w, wB, a0.w);
        a1.x = fmaf(uB1.x, wB, a1.x); a1.y = fmaf(uB1.y, wB, a1.y);
        a1.z = fmaf(uB1.z, wB, a1.z); a1.w = fmaf(uB1.w, wB, a1.w);
    }
    for (; j < j1; ++j) {
        int s = csr_src[j];
        float w = dis[s] * dd;
        const float4* r = reinterpret_cast<const float4*>(hw + (size_t)s * H);
        float4 u0 = r[lane * 2 + 0], u1 = r[lane * 2 + 1];
        a0.x = fmaf(u0.x, w, a0.x); a0.y = fmaf(u0.y, w, a0.y);
        a0.z = fmaf(u0.z, w, a0.z); a0.w = fmaf(u0.w, w, a0.w);
        a1.x = fmaf(u1.x, w, a1.x); a1.y = fmaf(u1.y, w, a1.y);
        a1.z = fmaf(u1.z, w, a1.z); a1.w = fmaf(u1.w, w, a1.w);
    }

    // relu + store
    a0.x = fmaxf(a0.x, 0.f); a0.y = fmaxf(a0.y, 0.f);
    a0.z = fmaxf(a0.z, 0.f); a0.w = fmaxf(a0.w, 0.f);
    a1.x = fmaxf(a1.x, 0.f); a1.y = fmaxf(a1.y, 0.f);
    a1.z = fmaxf(a1.z, 0.f); a1.w = fmaxf(a1.w, 0.f);

    float4* out = reinterpret_cast<float4*>(hout + (size_t)node * H);
    out[lane * 2 + 0] = a0;
    out[lane * 2 + 1] = a1;
}

// ---------------- mean over nodes ----------------
__global__ void mean_kernel(const float* __restrict__ h, float* __restrict__ mean, int n) {
    float acc = 0.0f;
    for (int r = blockIdx.x; r < n; r += gridDim.x)
        acc += h[(size_t)r * H + threadIdx.x];
    atomicAdd(&mean[threadIdx.x], acc);
}

// ---------------- head MLP ----------------
__global__ void head_kernel(const float* __restrict__ mean,
                            const float* __restrict__ W1, const float* __restrict__ b1,
                            const float* __restrict__ W2, const float* __restrict__ b2,
                            float* __restrict__ out, float invN)
{
    __shared__ float g[H];
    __shared__ float t[D_OUT];
    int tid = threadIdx.x;  // 128 threads
    g[tid]       = mean[tid]       * invN;
    g[tid + 128] = mean[tid + 128] * invN;
    __syncthreads();
    float acc = b1[tid];
    for (int k = 0; k < H; k++) acc = fmaf(g[k], W1[k * D_OUT + tid], acc);
    t[tid] = fmaxf(acc, 0.0f);
    __syncthreads();
    float acc2 = b2[tid];
    for (int k = 0; k < D_OUT; k++) acc2 = fmaf(t[k], W2[k * D_OUT + tid], acc2);
    out[tid] = acc2;
}

// ---------------- launch ----------------
extern "C" void kernel_launch(void* const* d_in, const int* in_sizes, int n_in,
                              void* d_out, int out_size)
{
    const float* x       = (const float*)d_in[0];
    const int*   eidx    = (const int*)  d_in[1];
    const float* W_enc1  = (const float*)d_in[3];
    const float* b_enc1  = (const float*)d_in[4];
    const float* W_enc2  = (const float*)d_in[5];
    const float* b_enc2  = (const float*)d_in[6];
    const float* W_g[3]  = { (const float*)d_in[8],  (const float*)d_in[10], (const float*)d_in[12] };
    const float* b_g[3]  = { (const float*)d_in[9],  (const float*)d_in[11], (const float*)d_in[13] };
    const float* W_h1    = (const float*)d_in[14];
    const float* b_h1    = (const float*)d_in[15];
    const float* W_h2    = (const float*)d_in[16];
    const float* b_h2    = (const float*)d_in[17];

    const int n = in_sizes[0] / D_IN;       // 50000
    const int E = in_sizes[2];              // 1600000
    const int* src = eidx;
    const int* dst = eidx + E;

    float *p_h, *p_hw, *p_dis, *p_mean;
    int *p_deg, *p_start, *p_cursor, *p_csr;
    cudaGetSymbolAddress((void**)&p_h,      g_h);
    cudaGetSymbolAddress((void**)&p_hw,     g_hw);
    cudaGetSymbolAddress((void**)&p_dis,    g_dis);
    cudaGetSymbolAddress((void**)&p_deg,    g_deg);
    cudaGetSymbolAddress((void**)&p_start,  g_start);
    cudaGetSymbolAddress((void**)&p_cursor, g_cursor);
    cudaGetSymbolAddress((void**)&p_csr,    g_csr_src);
    cudaGetSymbolAddress((void**)&p_mean,   g_mean);

    // 1) degrees, norm, CSR build
    cudaMemsetAsync(p_deg, 0, n * sizeof(int), 0);
    deg_kernel<<<(E + 255) / 256, 256>>>(dst, p_deg, E);
    dis_kernel<<<(n + 255) / 256, 256>>>(p_deg, p_dis, n);
    scan_kernel<<<1, 1024>>>(p_deg, p_start, p_cursor, n);
    fill_csr_kernel<<<(E + 255) / 256, 256>>>(src, dst, p_cursor, p_csr, E);

    dim3 gemmBlock(256);
    dim3 gemmGrid(H / 128, (n + 127) / 128);

    // 2) encoder: h = relu(x@W1+b1)@W2+b2
    sgemm_kernel<<<gemmGrid, gemmBlock>>>(x,    W_enc1, b_enc1, p_hw, n, D_IN, H, 1);
    sgemm_kernel<<<gemmGrid, gemmBlock>>>(p_hw, W_enc2, b_enc2, p_h,  n, H,    H, 0);

    // 3) three GCN layers: hw = h@W ; h = relu(gather(hw) + self + bias)
    const int warpsPerBlock = 256 / 32;
    const int gatherBlocks = (n + warpsPerBlock - 1) / warpsPerBlock;
    for (int l = 0; l < 3; ++l) {
        sgemm_kernel<<<gemmGrid, gemmBlock>>>(p_h, W_g[l], nullptr, p_hw, n, H, H, 0);
        gather_kernel<<<gatherBlocks, 256>>>(p_hw, p_dis, b_g[l], p_start, p_csr, p_h, n);
    }

    // 4) mean pooling + head
    cudaMemsetAsync(p_mean, 0, H * sizeof(float), 0);
    mean_kernel<<<128, H>>>(p_h, p_mean, n);
    head_kernel<<<1, D_OUT>>>(p_mean, W_h1, b_h1, W_h2, b_h2, (float*)d_out, 1.0f / (float)n);
}

// round 3
// speedup vs baseline: 4.2383x; 1.8754x over previous
#include <cuda_runtime.h>
#include <cuda_bf16.h>
#include <cstdint>

#define NODES_MAX 50000
#define EDGES_MAX 1600000
#define H 256
#define D_IN 518
#define D_OUT 128

// ---------------- device scratch ----------------
__device__ float g_h  [NODES_MAX * H];
__device__ float g_hw [NODES_MAX * H];
__device__ float g_dis[NODES_MAX];
__device__ int   g_deg[NODES_MAX];
__device__ int   g_start[NODES_MAX + 1];
__device__ int   g_cursor[NODES_MAX];
__device__ int   g_csr_src[EDGES_MAX];
__device__ int   g_bsum[64];
__device__ int   g_boff[64];
__device__ float g_mean[H];

// ---------------- degree / normalization ----------------
__global__ void deg_kernel(const int* __restrict__ dst, int* __restrict__ deg, int E) {
    int i = blockIdx.x * blockDim.x + threadIdx.x;
    if (i < E) atomicAdd(&deg[dst[i]], 1);
}

__global__ void dis_kernel(const int* __restrict__ deg, float* __restrict__ dis, int n) {
    int i = blockIdx.x * blockDim.x + threadIdx.x;
    if (i < n) dis[i] = rsqrtf(1.0f + (float)deg[i]);
}

// ---------------- parallel scan (3 phases) ----------------
// phase 1: per-block (1024 elems) inclusive scan -> start[i+1] (local), block total -> bsum
__global__ void scan_block_kernel(const int* __restrict__ deg, int* __restrict__ start,
                                  int* __restrict__ bsum, int n)
{
    __shared__ int warpSums[32];
    int i = blockIdx.x * 1024 + threadIdx.x;
    int lane = threadIdx.x & 31, warp = threadIdx.x >> 5;
    int v = (i < n) ? deg[i] : 0;
    int inc = v;
#pragma unroll
    for (int off = 1; off < 32; off <<= 1) {
        int t = __shfl_up_sync(0xffffffff, inc, off);
        if (lane >= off) inc += t;
    }
    if (lane == 31) warpSums[warp] = inc;
    __syncthreads();
    if (warp == 0) {
        int s = warpSums[lane];
#pragma unroll
        for (int off = 1; off < 32; off <<= 1) {
            int t = __shfl_up_sync(0xffffffff, s, off);
            if (lane >= off) s += t;
        }
        warpSums[lane] = s;
    }
    __syncthreads();
    int add = (warp > 0) ? warpSums[warp - 1] : 0;
    inc += add;
    if (i < n) start[i + 1] = inc;             // local inclusive
    if (threadIdx.x == 1023) bsum[blockIdx.x] = inc;
}

// phase 2: exclusive scan of block sums (single block, <=64 blocks)
__global__ void scan_sums_kernel(const int* __restrict__ bsum, int* __restrict__ boff, int nb) {
    int lane = threadIdx.x;  // 64 threads
    int v = (lane < nb) ? bsum[lane] : 0;
    int inc = v;
#pragma unroll
    for (int off = 1; off < 64; off <<= 1) {
        int t = __shfl_up_sync(0xffffffff, inc, off & 31);
        // do a proper two-warp scan via smem instead
    }
    // simple smem scan (64 elems)
    __shared__ int s[64];
    s[lane] = v;
    __syncthreads();
    for (int off = 1; off < 64; off <<= 1) {
        int t = (lane >= off) ? s[lane - off] : 0;
        __syncthreads();
        s[lane] += t;
        __syncthreads();
    }
    if (lane < nb) boff[lane] = (lane > 0) ? s[lane - 1] : 0;
}

// phase 3: add block offsets, produce cursor
__global__ void scan_finalize_kernel(const int* __restrict__ deg, int* __restrict__ start,
                                     const int* __restrict__ boff, int* __restrict__ cursor, int n)
{
    int i = blockIdx.x * blockDim.x + threadIdx.x;
    if (i < n) {
        int s = start[i + 1] + boff[i >> 10];
        start[i + 1] = s;
        cursor[i] = s - deg[i];
        if (i == 0) start[0] = 0;
    }
}

// ---------------- bucket edges by dst ----------------
__global__ void fill_csr_kernel(const int* __restrict__ src, const int* __restrict__ dst,
                                int* __restrict__ cursor, int* __restrict__ csr_src, int E)
{
    int e = blockIdx.x * blockDim.x + threadIdx.x;
    if (e < E) {
        int d = dst[e];
        int p = atomicAdd(&cursor[d], 1);
        csr_src[p] = src[e];
    }
}

// ---------------- tf32 tensor-core GEMM ----------------
// C[N,M] = A[N,K] @ B[K,M] (+bias)(+relu). Block 128x128xBK16, 8 warps, warp tile 64x32.
__global__ __launch_bounds__(256)
void tf32_gemm_kernel(const float* __restrict__ A, const float* __restrict__ B,
                      const float* __restrict__ bias, float* __restrict__ C,
                      int N, int K, int M, int doRelu)
{
    const int BM = 128, BN = 128, BK = 16;
    const int LDS_PAD = 136;   // 136 % 32 = 8 -> conflict-free fragment loads
    __shared__ uint32_t As[BK][LDS_PAD];   // As[k][m], tf32
    __shared__ uint32_t Bs[BK][LDS_PAD];   // Bs[k][n], tf32

    int tid = threadIdx.x;
    int wid = tid >> 5, lane = tid & 31;
    int warp_m = (wid & 1) * 64;     // 2 warp rows
    int warp_n = (wid >> 1) * 32;    // 4 warp cols
    int lq = lane & 3;               // quad lane (k offset)
    int lg = lane >> 2;              // group id (m/n offset)

    int row0 = blockIdx.y * BM;
    int col0 = blockIdx.x * BN;

    float c[4][4][4];
#pragma unroll
    for (int mi = 0; mi < 4; mi++)
#pragma unroll
        for (int ni = 0; ni < 4; ni++)
#pragma unroll
            for (int r = 0; r < 4; r++) c[mi][ni][r] = 0.0f;

    for (int k0 = 0; k0 < K; k0 += BK) {
        // --- load A tile (transposed into As[k][m]) ---
#pragma unroll
        for (int it = 0; it < 8; ++it) {
            int idx = it * 256 + tid;
            int m = idx >> 4, k = idx & 15;
            int gm = row0 + m, gk = k0 + k;
            float v = 0.0f;
            if (gm < N && gk < K) v = A[(size_t)gm * K + gk];
            uint32_t u;
            asm("cvt.rna.tf32.f32 %0, %1;" : "=r"(u) : "f"(v));
            As[k][m] = u;
        }
        // --- load B tile (Bs[k][n]) ---
#pragma unroll
        for (int it = 0; it < 2; ++it) {
            int idx4 = it * 256 + tid;
            int k = idx4 >> 5, cc = (idx4 & 31) * 4;
            int gk = k0 + k;
            float4 v = make_float4(0.f, 0.f, 0.f, 0.f);
            if (gk < K) v = *reinterpret_cast<const float4*>(&B[(size_t)gk * M + col0 + cc]);
            uint32_t u0, u1, u2, u3;
            asm("cvt.rna.tf32.f32 %0, %1;" : "=r"(u0) : "f"(v.x));
            asm("cvt.rna.tf32.f32 %0, %1;" : "=r"(u1) : "f"(v.y));
            asm("cvt.rna.tf32.f32 %0, %1;" : "=r"(u2) : "f"(v.z));
            asm("cvt.rna.tf32.f32 %0, %1;" : "=r"(u3) : "f"(v.w));
            Bs[k][cc + 0] = u0; Bs[k][cc + 1] = u1;
            Bs[k][cc + 2] = u2; Bs[k][cc + 3] = u3;
        }
        __syncthreads();

#pragma unroll
        for (int kk = 0; kk < BK; kk += 8) {
            uint32_t af[4][4], bf[4][2];
#pragma unroll
            for (int mi = 0; mi < 4; mi++) {
                int mrow = warp_m + mi * 16 + lg;
                af[mi][0] = As[kk + lq    ][mrow];
                af[mi][1] = As[kk + lq    ][mrow + 8];
                af[mi][2] = As[kk + lq + 4][mrow];
                af[mi][3] = As[kk + lq + 4][mrow + 8];
            }
#pragma unroll
            for (int ni = 0; ni < 4; ni++) {
                int ncol = warp_n + ni * 8 + lg;
                bf[ni][0] = Bs[kk + lq    ][ncol];
                bf[ni][1] = Bs[kk + lq + 4][ncol];
            }
#pragma unroll
            for (int mi = 0; mi < 4; mi++)
#pragma unroll
                for (int ni = 0; ni < 4; ni++) {
                    asm volatile(
                        "mma.sync.aligned.m16n8k8.row.col.f32.tf32.tf32.f32 "
                        "{%0,%1,%2,%3}, {%4,%5,%6,%7}, {%8,%9}, {%0,%1,%2,%3};"
                        : "+f"(c[mi][ni][0]), "+f"(c[mi][ni][1]),
                          "+f"(c[mi][ni][2]), "+f"(c[mi][ni][3])
                        : "r"(af[mi][0]), "r"(af[mi][1]), "r"(af[mi][2]), "r"(af[mi][3]),
                          "r"(bf[ni][0]), "r"(bf[ni][1]));
                }
        }
        __syncthreads();
    }

    // --- epilogue ---
#pragma unroll
    for (int mi = 0; mi < 4; mi++) {
#pragma unroll
        for (int ni = 0; ni < 4; ni++) {
            int r = row0 + warp_m + mi * 16 + lg;
            int cc = col0 + warp_n + ni * 8 + lq * 2;
            float v0 = c[mi][ni][0], v1 = c[mi][ni][1];
            float v2 = c[mi][ni][2], v3 = c[mi][ni][3];
            if (bias) {
                float bA = bias[cc], bB = bias[cc + 1];
                v0 += bA; v1 += bB; v2 += bA; v3 += bB;
            }
            if (doRelu) {
                v0 = fmaxf(v0, 0.f); v1 = fmaxf(v1, 0.f);
                v2 = fmaxf(v2, 0.f); v3 = fmaxf(v3, 0.f);
            }
            if (r < N) {
                C[(size_t)r * M + cc]     = v0;
                C[(size_t)r * M + cc + 1] = v1;
            }
            if (r + 8 < N) {
                C[(size_t)(r + 8) * M + cc]     = v2;
                C[(size_t)(r + 8) * M + cc + 1] = v3;
            }
        }
    }
}

// ---------------- fused GCN aggregation (gather form) ----------------
__global__ __launch_bounds__(256)
void gather_kernel(const float* __restrict__ hw, const float* __restrict__ dis,
                   const float* __restrict__ b,
                   const int* __restrict__ start, const int* __restrict__ csr_src,
                   float* __restrict__ hout, int n)
{
    int warp = (blockIdx.x * blockDim.x + threadIdx.x) >> 5;
    if (warp >= n) return;
    int lane = threadIdx.x & 31;
    int node = warp;

    float dd = dis[node];
    float self = dd * dd;

    const float4* hrow = reinterpret_cast<const float4*>(hw + (size_t)node * H);
    const float4* bb   = reinterpret_cast<const float4*>(b);
    float4 v0 = hrow[lane * 2 + 0];
    float4 v1 = hrow[lane * 2 + 1];
    float4 b0 = bb[lane * 2 + 0];
    float4 b1 = bb[lane * 2 + 1];

    float4 a0, a1;
    a0.x = fmaf(v0.x, self, b0.x); a0.y = fmaf(v0.y, self, b0.y);
    a0.z = fmaf(v0.z, self, b0.z); a0.w = fmaf(v0.w, self, b0.w);
    a1.x = fmaf(v1.x, self, b1.x); a1.y = fmaf(v1.y, self, b1.y);
    a1.z = fmaf(v1.z, self, b1.z); a1.w = fmaf(v1.w, self, b1.w);

    int j0 = start[node], j1 = start[node + 1];

    int j = j0;
    for (; j + 2 <= j1; j += 2) {
        int sA = csr_src[j];
        int sB = csr_src[j + 1];
        float wA = dis[sA] * dd;
        float wB = dis[sB] * dd;
        const float4* rA = reinterpret_cast<const float4*>(hw + (size_t)sA * H);
        const float4* rB = reinterpret_cast<const float4*>(hw + (size_t)sB * H);
        float4 uA0 = rA[lane * 2 + 0], uA1 = rA[lane * 2 + 1];
        float4 uB0 = rB[lane * 2 + 0], uB1 = rB[lane * 2 + 1];
        a0.x = fmaf(uA0.x, wA, a0.x); a0.y = fmaf(uA0.y, wA, a0.y);
        a0.z = fmaf(uA0.z, wA, a0.z); a0.w = fmaf(uA0.w, wA, a0.w);
        a1.x = fmaf(uA1.x, wA, a1.x); a1.y = fmaf(uA1.y, wA, a1.y);
        a1.z = fmaf(uA1.z, wA, a1.z); a1.w = fmaf(uA1.w, wA, a1.w);
        a0.x = fmaf(uB0.x, wB, a0.x); a0.y = fmaf(uB0.y, wB, a0.y);
        a0.z = fmaf(uB0.z, wB, a0.z); a0.w = fmaf(uB0.w, wB, a0.w);
        a1.x = fmaf(uB1.x, wB, a1.x); a1.y = fmaf(uB1.y, wB, a1.y);
        a1.z = fmaf(uB1.z, wB, a1.z); a1.w = fmaf(uB1.w, wB, a1.w);
    }
    for (; j < j1; ++j) {
        int s = csr_src[j];
        float w = dis[s] * dd;
        const float4* r = reinterpret_cast<const float4*>(hw + (size_t)s * H);
        float4 u0 = r[lane * 2 + 0], u1 = r[lane * 2 + 1];
        a0.x = fmaf(u0.x, w, a0.x); a0.y = fmaf(u0.y, w, a0.y);
        a0.z = fmaf(u0.z, w, a0.z); a0.w = fmaf(u0.w, w, a0.w);
        a1.x = fmaf(u1.x, w, a1.x); a1.y = fmaf(u1.y, w, a1.y);
        a1.z = fmaf(u1.z, w, a1.z); a1.w = fmaf(u1.w, w, a1.w);
    }

    a0.x = fmaxf(a0.x, 0.f); a0.y = fmaxf(a0.y, 0.f);
    a0.z = fmaxf(a0.z, 0.f); a0.w = fmaxf(a0.w, 0.f);
    a1.x = fmaxf(a1.x, 0.f); a1.y = fmaxf(a1.y, 0.f);
    a1.z = fmaxf(a1.z, 0.f); a1.w = fmaxf(a1.w, 0.f);

    float4* out = reinterpret_cast<float4*>(hout + (size_t)node * H);
    out[lane * 2 + 0] = a0;
    out[lane * 2 + 1] = a1;
}

// ---------------- mean over nodes ----------------
__global__ void mean_kernel(const float* __restrict__ h, float* __restrict__ mean, int n) {
    float acc = 0.0f;
    for (int r = blockIdx.x; r < n; r += gridDim.x)
        acc += h[(size_t)r * H + threadIdx.x];
    atomicAdd(&mean[threadIdx.x], acc);
}

// ---------------- head MLP ----------------
__global__ void head_kernel(const float* __restrict__ mean,
                            const float* __restrict__ W1, const float* __restrict__ b1,
                            const float* __restrict__ W2, const float* __restrict__ b2,
                            float* __restrict__ out, float invN)
{
    __shared__ float g[H];
    __shared__ float t[D_OUT];
    int tid = threadIdx.x;  // 128 threads
    g[tid]       = mean[tid]       * invN;
    g[tid + 128] = mean[tid + 128] * invN;
    __syncthreads();
    float acc = b1[tid];
    for (int k = 0; k < H; k++) acc = fmaf(g[k], W1[k * D_OUT + tid], acc);
    t[tid] = fmaxf(acc, 0.0f);
    __syncthreads();
    float acc2 = b2[tid];
    for (int k = 0; k < D_OUT; k++) acc2 = fmaf(t[k], W2[k * D_OUT + tid], acc2);
    out[tid] = acc2;
}

// ---------------- launch ----------------
extern "C" void kernel_launch(void* const* d_in, const int* in_sizes, int n_in,
                              void* d_out, int out_size)
{
    const float* x       = (const float*)d_in[0];
    const int*   eidx    = (const int*)  d_in[1];
    const float* W_enc1  = (const float*)d_in[3];
    const float* b_enc1  = (const float*)d_in[4];
    const float* W_enc2  = (const float*)d_in[5];
    const float* b_enc2  = (const float*)d_in[6];
    const float* W_g[3]  = { (const float*)d_in[8],  (const float*)d_in[10], (const float*)d_in[12] };
    const float* b_g[3]  = { (const float*)d_in[9],  (const float*)d_in[11], (const float*)d_in[13] };
    const float* W_h1    = (const float*)d_in[14];
    const float* b_h1    = (const float*)d_in[15];
    const float* W_h2    = (const float*)d_in[16];
    const float* b_h2    = (const float*)d_in[17];

    const int n = in_sizes[0] / D_IN;       // 50000
    const int E = in_sizes[2];              // 1600000
    const int* src = eidx;
    const int* dst = eidx + E;

    float *p_h, *p_hw, *p_dis, *p_mean;
    int *p_deg, *p_start, *p_cursor, *p_csr, *p_bsum, *p_boff;
    cudaGetSymbolAddress((void**)&p_h,      g_h);
    cudaGetSymbolAddress((void**)&p_hw,     g_hw);
    cudaGetSymbolAddress((void**)&p_dis,    g_dis);
    cudaGetSymbolAddress((void**)&p_deg,    g_deg);
    cudaGetSymbolAddress((void**)&p_start,  g_start);
    cudaGetSymbolAddress((void**)&p_cursor, g_cursor);
    cudaGetSymbolAddress((void**)&p_csr,    g_csr_src);
    cudaGetSymbolAddress((void**)&p_bsum,   g_bsum);
    cudaGetSymbolAddress((void**)&p_boff,   g_boff);
    cudaGetSymbolAddress((void**)&p_mean,   g_mean);

    // 1) degrees, norm, CSR build (parallel scan)
    cudaMemsetAsync(p_deg, 0, n * sizeof(int), 0);
    deg_kernel<<<(E + 255) / 256, 256>>>(dst, p_deg, E);
    dis_kernel<<<(n + 255) / 256, 256>>>(p_deg, p_dis, n);
    const int nScanBlocks = (n + 1023) / 1024;
    scan_block_kernel<<<nScanBlocks, 1024>>>(p_deg, p_start, p_bsum, n);
    scan_sums_kernel<<<1, 64>>>(p_bsum, p_boff, nScanBlocks);
    scan_finalize_kernel<<<(n + 255) / 256, 256>>>(p_deg, p_start, p_boff, p_cursor, n);
    fill_csr_kernel<<<(E + 255) / 256, 256>>>(src, dst, p_cursor, p_csr, E);

    dim3 gemmBlock(256);
    dim3 gemmGrid(H / 128, (n + 127) / 128);

    // 2) encoder
    tf32_gemm_kernel<<<gemmGrid, gemmBlock>>>(x,    W_enc1, b_enc1, p_hw, n, D_IN, H, 1);
    tf32_gemm_kernel<<<gemmGrid, gemmBlock>>>(p_hw, W_enc2, b_enc2, p_h,  n, H,    H, 0);

    // 3) three GCN layers
    const int warpsPerBlock = 256 / 32;
    const int gatherBlocks = (n + warpsPerBlock - 1) / warpsPerBlock;
    for (int l = 0; l < 3; ++l) {
        tf32_gemm_kernel<<<gemmGrid, gemmBlock>>>(p_h, W_g[l], nullptr, p_hw, n, H, H, 0);
        gather_kernel<<<gatherBlocks, 256>>>(p_hw, p_dis, b_g[l], p_start, p_csr, p_h, n);
    }

    // 4) mean pooling + head
    cudaMemsetAsync(p_mean, 0, H * sizeof(float), 0);
    mean_kernel<<<128, H>>>(p_h, p_mean, n);
    head_kernel<<<1, D_OUT>>>(p_mean, W_h1, b_h1, W_h2, b_h2, (float*)d_out, 1.0f / (float)n);
}

// round 4
// speedup vs baseline: 5.2215x; 1.2320x over previous
#include <cuda_runtime.h>
#include <cuda_fp16.h>
#include <cuda_bf16.h>
#include <cstdint>

#define NODES_MAX 50000
#define EDGES_MAX 1600000
#define H 256
#define D_IN 518
#define D_OUT 128

// ---------------- device scratch ----------------
__device__ float  g_h   [NODES_MAX * H];
__device__ float  g_hw  [NODES_MAX * H];
__device__ __half g_hw16[NODES_MAX * H];
__device__ float  g_dis[NODES_MAX];
__device__ int    g_deg[NODES_MAX];
__device__ int    g_start[NODES_MAX + 1];
__device__ int    g_cursor[NODES_MAX];
__device__ int    g_csr_src[EDGES_MAX];
__device__ int    g_bsum[64];
__device__ int    g_boff[64];
__device__ float  g_mean[H];

// ---------------- degree / normalization ----------------
__global__ void deg_kernel(const int* __restrict__ dst, int* __restrict__ deg, int E) {
    int i = blockIdx.x * blockDim.x + threadIdx.x;
    if (i < E) atomicAdd(&deg[dst[i]], 1);
}

__global__ void dis_kernel(const int* __restrict__ deg, float* __restrict__ dis, int n) {
    int i = blockIdx.x * blockDim.x + threadIdx.x;
    if (i < n) dis[i] = rsqrtf(1.0f + (float)deg[i]);
}

// ---------------- parallel scan (3 phases) ----------------
__global__ void scan_block_kernel(const int* __restrict__ deg, int* __restrict__ start,
                                  int* __restrict__ bsum, int n)
{
    __shared__ int warpSums[32];
    int i = blockIdx.x * 1024 + threadIdx.x;
    int lane = threadIdx.x & 31, warp = threadIdx.x >> 5;
    int v = (i < n) ? deg[i] : 0;
    int inc = v;
#pragma unroll
    for (int off = 1; off < 32; off <<= 1) {
        int t = __shfl_up_sync(0xffffffff, inc, off);
        if (lane >= off) inc += t;
    }
    if (lane == 31) warpSums[warp] = inc;
    __syncthreads();
    if (warp == 0) {
        int s = warpSums[lane];
#pragma unroll
        for (int off = 1; off < 32; off <<= 1) {
            int t = __shfl_up_sync(0xffffffff, s, off);
            if (lane >= off) s += t;
        }
        warpSums[lane] = s;
    }
    __syncthreads();
    int add = (warp > 0) ? warpSums[warp - 1] : 0;
    inc += add;
    if (i < n) start[i + 1] = inc;
    if (threadIdx.x == 1023) bsum[blockIdx.x] = inc;
}

__global__ void scan_sums_kernel(const int* __restrict__ bsum, int* __restrict__ boff, int nb) {
    int lane = threadIdx.x;  // 64 threads
    int v = (lane < nb) ? bsum[lane] : 0;
    __shared__ int s[64];
    s[lane] = v;
    __syncthreads();
    for (int off = 1; off < 64; off <<= 1) {
        int t = (lane >= off) ? s[lane - off] : 0;
        __syncthreads();
        s[lane] += t;
        __syncthreads();
    }
    if (lane < nb) boff[lane] = (lane > 0) ? s[lane - 1] : 0;
}

__global__ void scan_finalize_kernel(const int* __restrict__ deg, int* __restrict__ start,
                                     const int* __restrict__ boff, int* __restrict__ cursor, int n)
{
    int i = blockIdx.x * blockDim.x + threadIdx.x;
    if (i < n) {
        int s = start[i + 1] + boff[i >> 10];
        start[i + 1] = s;
        cursor[i] = s - deg[i];
        if (i == 0) start[0] = 0;
    }
}

// ---------------- bucket edges by dst ----------------
__global__ void fill_csr_kernel(const int* __restrict__ src, const int* __restrict__ dst,
                                int* __restrict__ cursor, int* __restrict__ csr_src, int E)
{
    int e = blockIdx.x * blockDim.x + threadIdx.x;
    if (e < E) {
        int d = dst[e];
        int p = atomicAdd(&cursor[d], 1);
        csr_src[p] = src[e];
    }
}

// ---------------- tf32 tensor-core GEMM, cp.async double-buffered ----------------
__device__ __forceinline__ uint32_t f2tf32(float x) {
    uint32_t u;
    asm("cvt.rna.tf32.f32 %0, %1;" : "=r"(u) : "f"(x));
    return u;
}

// C[N,M] = A[N,K] @ B[K,M] (+bias)(+relu)(+fp16 mirror)
__global__ __launch_bounds__(256)
void tf32_gemm_kernel(const float* __restrict__ A, const float* __restrict__ B,
                      const float* __restrict__ bias, float* __restrict__ C,
                      __half* __restrict__ C16,
                      int N, int K, int M, int doRelu)
{
    const int BM = 128, BN = 128, BK = 16, PAD = 136;
    __shared__ float As[2][BK][PAD];   // As[buf][k][m]
    __shared__ float Bs[2][BK][PAD];   // Bs[buf][k][n]

    int tid = threadIdx.x;
    int wid = tid >> 5, lane = tid & 31;
    int warp_m = (wid & 1) * 64;
    int warp_n = (wid >> 1) * 32;
    int lq = lane & 3;
    int lg = lane >> 2;

    int row0 = blockIdx.y * BM;
    int col0 = blockIdx.x * BN;
    int nt = (K + BK - 1) / BK;

    float c[4][4][4];
#pragma unroll
    for (int mi = 0; mi < 4; mi++)
#pragma unroll
        for (int ni = 0; ni < 4; ni++)
#pragma unroll
            for (int r = 0; r < 4; r++) c[mi][ni][r] = 0.0f;

    // tile loader: A via 4B zfill cp.async (transposed), B via 16B cp.async
    auto loadTile = [&](int t, int buf) {
        int k0 = t * BK;
#pragma unroll
        for (int it = 0; it < 8; ++it) {
            int idx = it * 256 + tid;
            int m = idx >> 4, k = idx & 15;
            int gm = row0 + m, gk = k0 + k;
            const float* src = A + (size_t)gm * K + gk;
            uint32_t dsh = (uint32_t)__cvta_generic_to_shared(&As[buf][k][m]);
            int sz = (gm < N && gk < K) ? 4 : 0;
            asm volatile("cp.async.ca.shared.global [%0], [%1], 4, %2;"
                         :: "r"(dsh), "l"(src), "r"(sz));
        }
#pragma unroll
        for (int it = 0; it < 2; ++it) {
            int idx4 = it * 256 + tid;
            int k = idx4 >> 5, cc = (idx4 & 31) * 4;
            int gk = k0 + k;
            const float* src = B + (size_t)gk * M + col0 + cc;
            uint32_t dsh = (uint32_t)__cvta_generic_to_shared(&Bs[buf][k][cc]);
            int sz = (gk < K) ? 16 : 0;
            asm volatile("cp.async.cg.shared.global [%0], [%1], 16, %2;"
                         :: "r"(dsh), "l"(src), "r"(sz));
        }
        asm volatile("cp.async.commit_group;");
    };

    loadTile(0, 0);
    for (int t = 0; t < nt; ++t) {
        int buf = t & 1;
        if (t + 1 < nt) {
            loadTile(t + 1, (t + 1) & 1);
            asm volatile("cp.async.wait_group 1;");
        } else {
            asm volatile("cp.async.wait_group 0;");
        }
        __syncthreads();

#pragma unroll
        for (int kk = 0; kk < BK; kk += 8) {
            uint32_t af[4][4], bf[4][2];
#pragma unroll
            for (int mi = 0; mi < 4; mi++) {
                int mrow = warp_m + mi * 16 + lg;
                af[mi][0] = f2tf32(As[buf][kk + lq    ][mrow]);
                af[mi][1] = f2tf32(As[buf][kk + lq    ][mrow + 8]);
                af[mi][2] = f2tf32(As[buf][kk + lq + 4][mrow]);
                af[mi][3] = f2tf32(As[buf][kk + lq + 4][mrow + 8]);
            }
#pragma unroll
            for (int ni = 0; ni < 4; ni++) {
                int ncol = warp_n + ni * 8 + lg;
                bf[ni][0] = f2tf32(Bs[buf][kk + lq    ][ncol]);
                bf[ni][1] = f2tf32(Bs[buf][kk + lq + 4][ncol]);
            }
#pragma unroll
            for (int mi = 0; mi < 4; mi++)
#pragma unroll
                for (int ni = 0; ni < 4; ni++) {
                    asm volatile(
                        "mma.sync.aligned.m16n8k8.row.col.f32.tf32.tf32.f32 "
                        "{%0,%1,%2,%3}, {%4,%5,%6,%7}, {%8,%9}, {%0,%1,%2,%3};"
                        : "+f"(c[mi][ni][0]), "+f"(c[mi][ni][1]),
                          "+f"(c[mi][ni][2]), "+f"(c[mi][ni][3])
                        : "r"(af[mi][0]), "r"(af[mi][1]), "r"(af[mi][2]), "r"(af[mi][3]),
                          "r"(bf[ni][0]), "r"(bf[ni][1]));
                }
        }
        __syncthreads();
    }

    // --- epilogue ---
#pragma unroll
    for (int mi = 0; mi < 4; mi++) {
#pragma unroll
        for (int ni = 0; ni < 4; ni++) {
            int r = row0 + warp_m + mi * 16 + lg;
            int cc = col0 + warp_n + ni * 8 + lq * 2;
            float v0 = c[mi][ni][0], v1 = c[mi][ni][1];
            float v2 = c[mi][ni][2], v3 = c[mi][ni][3];
            if (bias) {
                float bA = bias[cc], bB = bias[cc + 1];
                v0 += bA; v1 += bB; v2 += bA; v3 += bB;
            }
            if (doRelu) {
                v0 = fmaxf(v0, 0.f); v1 = fmaxf(v1, 0.f);
                v2 = fmaxf(v2, 0.f); v3 = fmaxf(v3, 0.f);
            }
            if (r < N) {
                C[(size_t)r * M + cc]     = v0;
                C[(size_t)r * M + cc + 1] = v1;
                if (C16) {
                    __half2 hv = __floats2half2_rn(v0, v1);
                    *reinterpret_cast<__half2*>(C16 + (size_t)r * M + cc) = hv;
                }
            }
            if (r + 8 < N) {
                C[(size_t)(r + 8) * M + cc]     = v2;
                C[(size_t)(r + 8) * M + cc + 1] = v3;
                if (C16) {
                    __half2 hv = __floats2half2_rn(v2, v3);
                    *reinterpret_cast<__half2*>(C16 + (size_t)(r + 8) * M + cc) = hv;
                }
            }
        }
    }
}

// ---------------- fused GCN aggregation: fp16 neighbor rows, fp32 accumulate ----------------
__global__ __launch_bounds__(256)
void gather_kernel(const float* __restrict__ hw, const __half* __restrict__ hw16,
                   const float* __restrict__ dis, const float* __restrict__ b,
                   const int* __restrict__ start, const int* __restrict__ csr_src,
                   float* __restrict__ hout, int n)
{
    int warp = (blockIdx.x * blockDim.x + threadIdx.x) >> 5;
    if (warp >= n) return;
    int lane = threadIdx.x & 31;
    int node = warp;

    float dd = dis[node];
    float self = dd * dd;

    const float4* hrow = reinterpret_cast<const float4*>(hw + (size_t)node * H);
    const float4* bb   = reinterpret_cast<const float4*>(b);
    float4 v0 = hrow[lane * 2 + 0];
    float4 v1 = hrow[lane * 2 + 1];
    float4 b0 = bb[lane * 2 + 0];
    float4 b1 = bb[lane * 2 + 1];

    float4 a0, a1;
    a0.x = fmaf(v0.x, self, b0.x); a0.y = fmaf(v0.y, self, b0.y);
    a0.z = fmaf(v0.z, self, b0.z); a0.w = fmaf(v0.w, self, b0.w);
    a1.x = fmaf(v1.x, self, b1.x); a1.y = fmaf(v1.y, self, b1.y);
    a1.z = fmaf(v1.z, self, b1.z); a1.w = fmaf(v1.w, self, b1.w);

    int j0 = start[node], j1 = start[node + 1];

    int j = j0;
    for (; j + 2 <= j1; j += 2) {
        int sA = csr_src[j];
        int sB = csr_src[j + 1];
        float wA = dis[sA] * dd;
        float wB = dis[sB] * dd;
        uint4 uA = *reinterpret_cast<const uint4*>(hw16 + (size_t)sA * H + lane * 8);
        uint4 uB = *reinterpret_cast<const uint4*>(hw16 + (size_t)sB * H + lane * 8);
        const __half2* hA = reinterpret_cast<const __half2*>(&uA);
        const __half2* hB = reinterpret_cast<const __half2*>(&uB);
        float2 fA0 = __half22float2(hA[0]), fA1 = __half22float2(hA[1]);
        float2 fA2 = __half22float2(hA[2]), fA3 = __half22float2(hA[3]);
        float2 fB0 = __half22float2(hB[0]), fB1 = __half22float2(hB[1]);
        float2 fB2 = __half22float2(hB[2]), fB3 = __half22float2(hB[3]);
        a0.x = fmaf(fA0.x, wA, a0.x); a0.y = fmaf(fA0.y, wA, a0.y);
        a0.z = fmaf(fA1.x, wA, a0.z); a0.w = fmaf(fA1.y, wA, a0.w);
        a1.x = fmaf(fA2.x, wA, a1.x); a1.y = fmaf(fA2.y, wA, a1.y);
        a1.z = fmaf(fA3.x, wA, a1.z); a1.w = fmaf(fA3.y, wA, a1.w);
        a0.x = fmaf(fB0.x, wB, a0.x); a0.y = fmaf(fB0.y, wB, a0.y);
        a0.z = fmaf(fB1.x, wB, a0.z); a0.w = fmaf(fB1.y, wB, a0.w);
        a1.x = fmaf(fB2.x, wB, a1.x); a1.y = fmaf(fB2.y, wB, a1.y);
        a1.z = fmaf(fB3.x, wB, a1.z); a1.w = fmaf(fB3.y, wB, a1.w);
    }
    for (; j < j1; ++j) {
        int s = csr_src[j];
        float w = dis[s] * dd;
        uint4 u = *reinterpret_cast<const uint4*>(hw16 + (size_t)s * H + lane * 8);
        const __half2* hp = reinterpret_cast<const __half2*>(&u);
        float2 f0 = __half22float2(hp[0]), f1 = __half22float2(hp[1]);
        float2 f2 = __half22float2(hp[2]), f3 = __half22float2(hp[3]);
        a0.x = fmaf(f0.x, w, a0.x); a0.y = fmaf(f0.y, w, a0.y);
        a0.z = fmaf(f1.x, w, a0.z); a0.w = fmaf(f1.y, w, a0.w);
        a1.x = fmaf(f2.x, w, a1.x); a1.y = fmaf(f2.y, w, a1.y);
        a1.z = fmaf(f3.x, w, a1.z); a1.w = fmaf(f3.y, w, a1.w);
    }

    a0.x = fmaxf(a0.x, 0.f); a0.y = fmaxf(a0.y, 0.f);
    a0.z = fmaxf(a0.z, 0.f); a0.w = fmaxf(a0.w, 0.f);
    a1.x = fmaxf(a1.x, 0.f); a1.y = fmaxf(a1.y, 0.f);
    a1.z = fmaxf(a1.z, 0.f); a1.w = fmaxf(a1.w, 0.f);

    float4* out = reinterpret_cast<float4*>(hout + (size_t)node * H);
    out[lane * 2 + 0] = a0;
    out[lane * 2 + 1] = a1;
}

// ---------------- mean over nodes ----------------
__global__ void mean_kernel(const float* __restrict__ h, float* __restrict__ mean, int n) {
    float acc = 0.0f;
    for (int r = blockIdx.x; r < n; r += gridDim.x)
        acc += h[(size_t)r * H + threadIdx.x];
    atomicAdd(&mean[threadIdx.x], acc);
}

// ---------------- head MLP ----------------
__global__ void head_kernel(const float* __restrict__ mean,
                            const float* __restrict__ W1, const float* __restrict__ b1,
                            const float* __restrict__ W2, const float* __restrict__ b2,
                            float* __restrict__ out, float invN)
{
    __shared__ float g[H];
    __shared__ float t[D_OUT];
    int tid = threadIdx.x;  // 128 threads
    g[tid]       = mean[tid]       * invN;
    g[tid + 128] = mean[tid + 128] * invN;
    __syncthreads();
    float acc = b1[tid];
    for (int k = 0; k < H; k++) acc = fmaf(g[k], W1[k * D_OUT + tid], acc);
    t[tid] = fmaxf(acc, 0.0f);
    __syncthreads();
    float acc2 = b2[tid];
    for (int k = 0; k < D_OUT; k++) acc2 = fmaf(t[k], W2[k * D_OUT + tid], acc2);
    out[tid] = acc2;
}

// ---------------- launch ----------------
extern "C" void kernel_launch(void* const* d_in, const int* in_sizes, int n_in,
                              void* d_out, int out_size)
{
    const float* x       = (const float*)d_in[0];
    const int*   eidx    = (const int*)  d_in[1];
    const float* W_enc1  = (const float*)d_in[3];
    const float* b_enc1  = (const float*)d_in[4];
    const float* W_enc2  = (const float*)d_in[5];
    const float* b_enc2  = (const float*)d_in[6];
    const float* W_g[3]  = { (const float*)d_in[8],  (const float*)d_in[10], (const float*)d_in[12] };
    const float* b_g[3]  = { (const float*)d_in[9],  (const float*)d_in[11], (const float*)d_in[13] };
    const float* W_h1    = (const float*)d_in[14];
    const float* b_h1    = (const float*)d_in[15];
    const float* W_h2    = (const float*)d_in[16];
    const float* b_h2    = (const float*)d_in[17];

    const int n = in_sizes[0] / D_IN;       // 50000
    const int E = in_sizes[2];              // 1600000
    const int* src = eidx;
    const int* dst = eidx + E;

    float *p_h, *p_hw, *p_dis, *p_mean;
    __half* p_hw16;
    int *p_deg, *p_start, *p_cursor, *p_csr, *p_bsum, *p_boff;
    cudaGetSymbolAddress((void**)&p_h,      g_h);
    cudaGetSymbolAddress((void**)&p_hw,     g_hw);
    cudaGetSymbolAddress((void**)&p_hw16,   g_hw16);
    cudaGetSymbolAddress((void**)&p_dis,    g_dis);
    cudaGetSymbolAddress((void**)&p_deg,    g_deg);
    cudaGetSymbolAddress((void**)&p_start,  g_start);
    cudaGetSymbolAddress((void**)&p_cursor, g_cursor);
    cudaGetSymbolAddress((void**)&p_csr,    g_csr_src);
    cudaGetSymbolAddress((void**)&p_bsum,   g_bsum);
    cudaGetSymbolAddress((void**)&p_boff,   g_boff);
    cudaGetSymbolAddress((void**)&p_mean,   g_mean);

    // 1) degrees, norm, CSR build
    cudaMemsetAsync(p_deg, 0, n * sizeof(int), 0);
    deg_kernel<<<(E + 255) / 256, 256>>>(dst, p_deg, E);
    dis_kernel<<<(n + 255) / 256, 256>>>(p_deg, p_dis, n);
    const int nScanBlocks = (n + 1023) / 1024;
    scan_block_kernel<<<nScanBlocks, 1024>>>(p_deg, p_start, p_bsum, n);
    scan_sums_kernel<<<1, 64>>>(p_bsum, p_boff, nScanBlocks);
    scan_finalize_kernel<<<(n + 255) / 256, 256>>>(p_deg, p_start, p_boff, p_cursor, n);
    fill_csr_kernel<<<(E + 255) / 256, 256>>>(src, dst, p_cursor, p_csr, E);

    dim3 gemmBlock(256);
    dim3 gemmGrid(H / 128, (n + 127) / 128);

    // 2) encoder
    tf32_gemm_kernel<<<gemmGrid, gemmBlock>>>(x,    W_enc1, b_enc1, p_hw, nullptr, n, D_IN, H, 1);
    tf32_gemm_kernel<<<gemmGrid, gemmBlock>>>(p_hw, W_enc2, b_enc2, p_h,  nullptr, n, H,    H, 0);

    // 3) three GCN layers
    const int warpsPerBlock = 256 / 32;
    const int gatherBlocks = (n + warpsPerBlock - 1) / warpsPerBlock;
    for (int l = 0; l < 3; ++l) {
        tf32_gemm_kernel<<<gemmGrid, gemmBlock>>>(p_h, W_g[l], nullptr, p_hw, p_hw16, n, H, H, 0);
        gather_kernel<<<gatherBlocks, 256>>>(p_hw, p_hw16, p_dis, b_g[l], p_start, p_csr, p_h, n);
    }

    // 4) mean pooling + head
    cudaMemsetAsync(p_mean, 0, H * sizeof(float), 0);
    mean_kernel<<<128, H>>>(p_h, p_mean, n);
    head_kernel<<<1, D_OUT>>>(p_mean, W_h1, b_h1, W_h2, b_h2, (float*)d_out, 1.0f / (float)n);
}

// round 5
// speedup vs baseline: 6.9940x; 1.3395x over previous
#include <cuda_runtime.h>
#include <cuda_fp16.h>
#include <cuda_bf16.h>
#include <cstdint>

#define NODES_MAX 50000
#define EDGES_MAX 1600000
#define H 256
#define D_IN 518
#define D_OUT 128

// ---------------- device scratch ----------------
__device__ __half g_h16 [NODES_MAX * H];   // layer activations (fp16)
__device__ __half g_hw16[NODES_MAX * H];   // GEMM outputs (fp16)
__device__ __half g_w16 [4 * H * H];       // transposed fp16 weights: enc2, g1, g2, g3
__device__ float  g_dis[NODES_MAX];
__device__ int    g_deg[NODES_MAX];
__device__ int    g_start[NODES_MAX + 1];
__device__ int    g_cursor[NODES_MAX];
__device__ int    g_csr_src[EDGES_MAX];
__device__ int    g_bsum[64];
__device__ int    g_boff[64];
__device__ float  g_mean[H];

// ---------------- degree / normalization ----------------
__global__ void deg_kernel(const int* __restrict__ dst, int* __restrict__ deg, int E) {
    int i = blockIdx.x * blockDim.x + threadIdx.x;
    if (i < E) atomicAdd(&deg[dst[i]], 1);
}

__global__ void dis_kernel(const int* __restrict__ deg, float* __restrict__ dis, int n) {
    int i = blockIdx.x * blockDim.x + threadIdx.x;
    if (i < n) dis[i] = rsqrtf(1.0f + (float)deg[i]);
}

// ---------------- parallel scan (3 phases) ----------------
__global__ void scan_block_kernel(const int* __restrict__ deg, int* __restrict__ start,
                                  int* __restrict__ bsum, int n)
{
    __shared__ int warpSums[32];
    int i = blockIdx.x * 1024 + threadIdx.x;
    int lane = threadIdx.x & 31, warp = threadIdx.x >> 5;
    int v = (i < n) ? deg[i] : 0;
    int inc = v;
#pragma unroll
    for (int off = 1; off < 32; off <<= 1) {
        int t = __shfl_up_sync(0xffffffff, inc, off);
        if (lane >= off) inc += t;
    }
    if (lane == 31) warpSums[warp] = inc;
    __syncthreads();
    if (warp == 0) {
        int s = warpSums[lane];
#pragma unroll
        for (int off = 1; off < 32; off <<= 1) {
            int t = __shfl_up_sync(0xffffffff, s, off);
            if (lane >= off) s += t;
        }
        warpSums[lane] = s;
    }
    __syncthreads();
    int add = (warp > 0) ? warpSums[warp - 1] : 0;
    inc += add;
    if (i < n) start[i + 1] = inc;
    if (threadIdx.x == 1023) bsum[blockIdx.x] = inc;
}

__global__ void scan_sums_kernel(const int* __restrict__ bsum, int* __restrict__ boff, int nb) {
    int lane = threadIdx.x;  // 64 threads
    int v = (lane < nb) ? bsum[lane] : 0;
    __shared__ int s[64];
    s[lane] = v;
    __syncthreads();
    for (int off = 1; off < 64; off <<= 1) {
        int t = (lane >= off) ? s[lane - off] : 0;
        __syncthreads();
        s[lane] += t;
        __syncthreads();
    }
    if (lane < nb) boff[lane] = (lane > 0) ? s[lane - 1] : 0;
}

__global__ void scan_finalize_kernel(const int* __restrict__ deg, int* __restrict__ start,
                                     const int* __restrict__ boff, int* __restrict__ cursor, int n)
{
    int i = blockIdx.x * blockDim.x + threadIdx.x;
    if (i < n) {
        int s = start[i + 1] + boff[i >> 10];
        start[i + 1] = s;
        cursor[i] = s - deg[i];
        if (i == 0) start[0] = 0;
    }
}

// ---------------- bucket edges by dst ----------------
__global__ void fill_csr_kernel(const int* __restrict__ src, const int* __restrict__ dst,
                                int* __restrict__ cursor, int* __restrict__ csr_src, int E)
{
    int e = blockIdx.x * blockDim.x + threadIdx.x;
    if (e < E) {
        int d = dst[e];
        int p = atomicAdd(&cursor[d], 1);
        csr_src[p] = src[e];
    }
}

// ---------------- weight transpose + fp16 convert: WT[m][k] = W[k][m] ----------------
__global__ void wtrans_kernel(const float* __restrict__ W, __half* __restrict__ WT, int K, int M) {
    int idx = blockIdx.x * blockDim.x + threadIdx.x;
    if (idx < K * M) {
        int m = idx / K, k = idx % K;
        WT[(size_t)m * K + k] = __float2half_rn(W[(size_t)k * M + m]);
    }
}

// ---------------- tf32 tensor-core GEMM (fp32 A input; used for encoder L1) ----------------
__device__ __forceinline__ uint32_t f2tf32(float x) {
    uint32_t u;
    asm("cvt.rna.tf32.f32 %0, %1;" : "=r"(u) : "f"(x));
    return u;
}

__global__ __launch_bounds__(256)
void tf32_gemm_kernel(const float* __restrict__ A, const float* __restrict__ B,
                      const float* __restrict__ bias, float* __restrict__ C,
                      __half* __restrict__ C16,
                      int N, int K, int M, int doRelu)
{
    const int BM = 128, BN = 128, BK = 16, PAD = 136;
    __shared__ float As[2][BK][PAD];
    __shared__ float Bs[2][BK][PAD];

    int tid = threadIdx.x;
    int wid = tid >> 5, lane = tid & 31;
    int warp_m = (wid & 1) * 64;
    int warp_n = (wid >> 1) * 32;
    int lq = lane & 3;
    int lg = lane >> 2;

    int row0 = blockIdx.y * BM;
    int col0 = blockIdx.x * BN;
    int nt = (K + BK - 1) / BK;

    float c[4][4][4];
#pragma unroll
    for (int mi = 0; mi < 4; mi++)
#pragma unroll
        for (int ni = 0; ni < 4; ni++)
#pragma unroll
            for (int r = 0; r < 4; r++) c[mi][ni][r] = 0.0f;

    auto loadTile = [&](int t, int buf) {
        int k0 = t * BK;
#pragma unroll
        for (int it = 0; it < 8; ++it) {
            int idx = it * 256 + tid;
            int m = idx >> 4, k = idx & 15;
            int gm = row0 + m, gk = k0 + k;
            const float* src = A + (size_t)gm * K + gk;
            uint32_t dsh = (uint32_t)__cvta_generic_to_shared(&As[buf][k][m]);
            int sz = (gm < N && gk < K) ? 4 : 0;
            asm volatile("cp.async.ca.shared.global [%0], [%1], 4, %2;"
                         :: "r"(dsh), "l"(src), "r"(sz));
        }
#pragma unroll
        for (int it = 0; it < 2; ++it) {
            int idx4 = it * 256 + tid;
            int k = idx4 >> 5, cc = (idx4 & 31) * 4;
            int gk = k0 + k;
            const float* src = B + (size_t)gk * M + col0 + cc;
            uint32_t dsh = (uint32_t)__cvta_generic_to_shared(&Bs[buf][k][cc]);
            int sz = (gk < K) ? 16 : 0;
            asm volatile("cp.async.cg.shared.global [%0], [%1], 16, %2;"
                         :: "r"(dsh), "l"(src), "r"(sz));
        }
        asm volatile("cp.async.commit_group;");
    };

    loadTile(0, 0);
    for (int t = 0; t < nt; ++t) {
        int buf = t & 1;
        if (t + 1 < nt) {
            loadTile(t + 1, (t + 1) & 1);
            asm volatile("cp.async.wait_group 1;");
        } else {
            asm volatile("cp.async.wait_group 0;");
        }
        __syncthreads();

#pragma unroll
        for (int kk = 0; kk < BK; kk += 8) {
            uint32_t af[4][4], bf[4][2];
#pragma unroll
            for (int mi = 0; mi < 4; mi++) {
                int mrow = warp_m + mi * 16 + lg;
                af[mi][0] = f2tf32(As[buf][kk + lq    ][mrow]);
                af[mi][1] = f2tf32(As[buf][kk + lq    ][mrow + 8]);
                af[mi][2] = f2tf32(As[buf][kk + lq + 4][mrow]);
                af[mi][3] = f2tf32(As[buf][kk + lq + 4][mrow + 8]);
            }
#pragma unroll
            for (int ni = 0; ni < 4; ni++) {
                int ncol = warp_n + ni * 8 + lg;
                bf[ni][0] = f2tf32(Bs[buf][kk + lq    ][ncol]);
                bf[ni][1] = f2tf32(Bs[buf][kk + lq + 4][ncol]);
            }
#pragma unroll
            for (int mi = 0; mi < 4; mi++)
#pragma unroll
                for (int ni = 0; ni < 4; ni++) {
                    asm volatile(
                        "mma.sync.aligned.m16n8k8.row.col.f32.tf32.tf32.f32 "
                        "{%0,%1,%2,%3}, {%4,%5,%6,%7}, {%8,%9}, {%0,%1,%2,%3};"
                        : "+f"(c[mi][ni][0]), "+f"(c[mi][ni][1]),
                          "+f"(c[mi][ni][2]), "+f"(c[mi][ni][3])
                        : "r"(af[mi][0]), "r"(af[mi][1]), "r"(af[mi][2]), "r"(af[mi][3]),
                          "r"(bf[ni][0]), "r"(bf[ni][1]));
                }
        }
        __syncthreads();
    }

#pragma unroll
    for (int mi = 0; mi < 4; mi++) {
#pragma unroll
        for (int ni = 0; ni < 4; ni++) {
            int r = row0 + warp_m + mi * 16 + lg;
            int cc = col0 + warp_n + ni * 8 + lq * 2;
            float v0 = c[mi][ni][0], v1 = c[mi][ni][1];
            float v2 = c[mi][ni][2], v3 = c[mi][ni][3];
            if (bias) {
                float bA = bias[cc], bB = bias[cc + 1];
                v0 += bA; v1 += bB; v2 += bA; v3 += bB;
            }
            if (doRelu) {
                v0 = fmaxf(v0, 0.f); v1 = fmaxf(v1, 0.f);
                v2 = fmaxf(v2, 0.f); v3 = fmaxf(v3, 0.f);
            }
            if (r < N) {
                if (C) {
                    C[(size_t)r * M + cc]     = v0;
                    C[(size_t)r * M + cc + 1] = v1;
                }
                if (C16)
                    *reinterpret_cast<__half2*>(C16 + (size_t)r * M + cc) = __floats2half2_rn(v0, v1);
            }
            if (r + 8 < N) {
                if (C) {
                    C[(size_t)(r + 8) * M + cc]     = v2;
                    C[(size_t)(r + 8) * M + cc + 1] = v3;
                }
                if (C16)
                    *reinterpret_cast<__half2*>(C16 + (size_t)(r + 8) * M + cc) = __floats2half2_rn(v2, v3);
            }
        }
    }
}

// ---------------- fp16 tensor-core GEMM ----------------
// C16[N,M] = A16[N,K] @ WT16[M,K]^T (+bias)(+relu), fp32 accumulate.
// A row-major [N,K] fp16, B given TRANSPOSED [M,K] fp16. K multiple of 16.
__global__ __launch_bounds__(256)
void fp16_gemm_kernel(const __half* __restrict__ A, const __half* __restrict__ BT,
                      const float* __restrict__ bias, __half* __restrict__ C16,
                      int N, int K, int M, int doRelu)
{
    const int BM = 128, BN = 128, BK = 16, PAD = 24;  // 24 halves = 48B row stride
    __shared__ alignas(16) __half Ah[2][BM][PAD];     // Ah[buf][m][k]
    __shared__ alignas(16) __half Bh[2][BN][PAD];     // Bh[buf][n][k]

    int tid = threadIdx.x;
    int wid = tid >> 5, lane = tid & 31;
    int warp_m = (wid & 1) * 64;
    int warp_n = (wid >> 1) * 32;
    int lq = lane & 3;
    int lg = lane >> 2;

    int row0 = blockIdx.y * BM;
    int col0 = blockIdx.x * BN;
    int nt = K / BK;

    float c[4][4][4];
#pragma unroll
    for (int mi = 0; mi < 4; mi++)
#pragma unroll
        for (int ni = 0; ni < 4; ni++)
#pragma unroll
            for (int r = 0; r < 4; r++) c[mi][ni][r] = 0.0f;

    // each thread loads one 16B chunk of A and one of B per tile
    int ldRow = tid >> 1;            // 0..127
    int ldCol = (tid & 1) * 8;       // 0 or 8 (halves)

    auto loadTile = [&](int t, int buf) {
        int k0 = t * BK;
        {
            int gm = row0 + ldRow;
            const __half* src = A + (size_t)gm * K + k0 + ldCol;
            uint32_t dsh = (uint32_t)__cvta_generic_to_shared(&Ah[buf][ldRow][ldCol]);
            int sz = (gm < N) ? 16 : 0;
            asm volatile("cp.async.cg.shared.global [%0], [%1], 16, %2;"
                         :: "r"(dsh), "l"(src), "r"(sz));
        }
        {
            int gn = col0 + ldRow;   // always < M (M=256)
            const __half* src = BT + (size_t)gn * K + k0 + ldCol;
            uint32_t dsh = (uint32_t)__cvta_generic_to_shared(&Bh[buf][ldRow][ldCol]);
            asm volatile("cp.async.cg.shared.global [%0], [%1], 16;"
                         :: "r"(dsh), "l"(src));
        }
        asm volatile("cp.async.commit_group;");
    };

    loadTile(0, 0);
    for (int t = 0; t < nt; ++t) {
        int buf = t & 1;
        if (t + 1 < nt) {
            loadTile(t + 1, (t + 1) & 1);
            asm volatile("cp.async.wait_group 1;");
        } else {
            asm volatile("cp.async.wait_group 0;");
        }
        __syncthreads();

        int kc = lq * 2;
        uint32_t af[4][4], bf[4][2];
#pragma unroll
        for (int mi = 0; mi < 4; mi++) {
            int mrow = warp_m + mi * 16 + lg;
            af[mi][0] = *reinterpret_cast<const uint32_t*>(&Ah[buf][mrow    ][kc    ]);
            af[mi][1] = *reinterpret_cast<const uint32_t*>(&Ah[buf][mrow + 8][kc    ]);
            af[mi][2] = *reinterpret_cast<const uint32_t*>(&Ah[buf][mrow    ][kc + 8]);
            af[mi][3] = *reinterpret_cast<const uint32_t*>(&Ah[buf][mrow + 8][kc + 8]);
        }
#pragma unroll
        for (int ni = 0; ni < 4; ni++) {
            int ncol = warp_n + ni * 8 + lg;
            bf[ni][0] = *reinterpret_cast<const uint32_t*>(&Bh[buf][ncol][kc    ]);
            bf[ni][1] = *reinterpret_cast<const uint32_t*>(&Bh[buf][ncol][kc + 8]);
        }
#pragma unroll
        for (int mi = 0; mi < 4; mi++)
#pragma unroll
            for (int ni = 0; ni < 4; ni++) {
                asm volatile(
                    "mma.sync.aligned.m16n8k16.row.col.f32.f16.f16.f32 "
                    "{%0,%1,%2,%3}, {%4,%5,%6,%7}, {%8,%9}, {%0,%1,%2,%3};"
                    : "+f"(c[mi][ni][0]), "+f"(c[mi][ni][1]),
                      "+f"(c[mi][ni][2]), "+f"(c[mi][ni][3])
                    : "r"(af[mi][0]), "r"(af[mi][1]), "r"(af[mi][2]), "r"(af[mi][3]),
                      "r"(bf[ni][0]), "r"(bf[ni][1]));
            }
        __syncthreads();
    }

#pragma unroll
    for (int mi = 0; mi < 4; mi++) {
#pragma unroll
        for (int ni = 0; ni < 4; ni++) {
            int r = row0 + warp_m + mi * 16 + lg;
            int cc = col0 + warp_n + ni * 8 + lq * 2;
            float v0 = c[mi][ni][0], v1 = c[mi][ni][1];
            float v2 = c[mi][ni][2], v3 = c[mi][ni][3];
            if (bias) {
                float bA = bias[cc], bB = bias[cc + 1];
                v0 += bA; v1 += bB; v2 += bA; v3 += bB;
            }
            if (doRelu) {
                v0 = fmaxf(v0, 0.f); v1 = fmaxf(v1, 0.f);
                v2 = fmaxf(v2, 0.f); v3 = fmaxf(v3, 0.f);
            }
            if (r < N)
                *reinterpret_cast<__half2*>(C16 + (size_t)r * M + cc) = __floats2half2_rn(v0, v1);
            if (r + 8 < N)
                *reinterpret_cast<__half2*>(C16 + (size_t)(r + 8) * M + cc) = __floats2half2_rn(v2, v3);
        }
    }
}

// ---------------- fused GCN aggregation: fp16 rows, fp32 accumulate, fp16 out ----------------
__global__ __launch_bounds__(256)
void gather_kernel(const __half* __restrict__ hw16,
                   const float* __restrict__ dis, const float* __restrict__ b,
                   const int* __restrict__ start, const int* __restrict__ csr_src,
                   __half* __restrict__ hout16, int n)
{
    int warp = (blockIdx.x * blockDim.x + threadIdx.x) >> 5;
    if (warp >= n) return;
    int lane = threadIdx.x & 31;
    int node = warp;

    float dd = dis[node];
    float self = dd * dd;

    // self term + bias
    uint4 us = *reinterpret_cast<const uint4*>(hw16 + (size_t)node * H + lane * 8);
    const __half2* hs = reinterpret_cast<const __half2*>(&us);
    const float4* bb = reinterpret_cast<const float4*>(b);
    float4 b0 = bb[lane * 2 + 0];
    float4 b1 = bb[lane * 2 + 1];
    float2 s0 = __half22float2(hs[0]), s1 = __half22float2(hs[1]);
    float2 s2 = __half22float2(hs[2]), s3 = __half22float2(hs[3]);

    float4 a0, a1;
    a0.x = fmaf(s0.x, self, b0.x); a0.y = fmaf(s0.y, self, b0.y);
    a0.z = fmaf(s1.x, self, b0.z); a0.w = fmaf(s1.y, self, b0.w);
    a1.x = fmaf(s2.x, self, b1.x); a1.y = fmaf(s2.y, self, b1.y);
    a1.z = fmaf(s3.x, self, b1.z); a1.w = fmaf(s3.y, self, b1.w);

    int j0 = start[node], j1 = start[node + 1];

    int j = j0;
    for (; j + 2 <= j1; j += 2) {
        int sA = csr_src[j];
        int sB = csr_src[j + 1];
        float wA = dis[sA] * dd;
        float wB = dis[sB] * dd;
        uint4 uA = *reinterpret_cast<const uint4*>(hw16 + (size_t)sA * H + lane * 8);
        uint4 uB = *reinterpret_cast<const uint4*>(hw16 + (size_t)sB * H + lane * 8);
        const __half2* hA = reinterpret_cast<const __half2*>(&uA);
        const __half2* hB = reinterpret_cast<const __half2*>(&uB);
        float2 fA0 = __half22float2(hA[0]), fA1 = __half22float2(hA[1]);
        float2 fA2 = __half22float2(hA[2]), fA3 = __half22float2(hA[3]);
        float2 fB0 = __half22float2(hB[0]), fB1 = __half22float2(hB[1]);
        float2 fB2 = __half22float2(hB[2]), fB3 = __half22float2(hB[3]);
        a0.x = fmaf(fA0.x, wA, a0.x); a0.y = fmaf(fA0.y, wA, a0.y);
        a0.z = fmaf(fA1.x, wA, a0.z); a0.w = fmaf(fA1.y, wA, a0.w);
        a1.x = fmaf(fA2.x, wA, a1.x); a1.y = fmaf(fA2.y, wA, a1.y);
        a1.z = fmaf(fA3.x, wA, a1.z); a1.w = fmaf(fA3.y, wA, a1.w);
        a0.x = fmaf(fB0.x, wB, a0.x); a0.y = fmaf(fB0.y, wB, a0.y);
        a0.z = fmaf(fB1.x, wB, a0.z); a0.w = fmaf(fB1.y, wB, a0.w);
        a1.x = fmaf(fB2.x, wB, a1.x); a1.y = fmaf(fB2.y, wB, a1.y);
        a1.z = fmaf(fB3.x, wB, a1.z); a1.w = fmaf(fB3.y, wB, a1.w);
    }
    for (; j < j1; ++j) {
        int s = csr_src[j];
        float w = dis[s] * dd;
        uint4 u = *reinterpret_cast<const uint4*>(hw16 + (size_t)s * H + lane * 8);
        const __half2* hp = reinterpret_cast<const __half2*>(&u);
        float2 f0 = __half22float2(hp[0]), f1 = __half22float2(hp[1]);
        float2 f2 = __half22float2(hp[2]), f3 = __half22float2(hp[3]);
        a0.x = fmaf(f0.x, w, a0.x); a0.y = fmaf(f0.y, w, a0.y);
        a0.z = fmaf(f1.x, w, a0.z); a0.w = fmaf(f1.y, w, a0.w);
        a1.x = fmaf(f2.x, w, a1.x); a1.y = fmaf(f2.y, w, a1.y);
        a1.z = fmaf(f3.x, w, a1.z); a1.w = fmaf(f3.y, w, a1.w);
    }

    a0.x = fmaxf(a0.x, 0.f); a0.y = fmaxf(a0.y, 0.f);
    a0.z = fmaxf(a0.z, 0.f); a0.w = fmaxf(a0.w, 0.f);
    a1.x = fmaxf(a1.x, 0.f); a1.y = fmaxf(a1.y, 0.f);
    a1.z = fmaxf(a1.z, 0.f); a1.w = fmaxf(a1.w, 0.f);

    uint4 outw;
    __half2* ho = reinterpret_cast<__half2*>(&outw);
    ho[0] = __floats2half2_rn(a0.x, a0.y);
    ho[1] = __floats2half2_rn(a0.z, a0.w);
    ho[2] = __floats2half2_rn(a1.x, a1.y);
    ho[3] = __floats2half2_rn(a1.z, a1.w);
    *reinterpret_cast<uint4*>(hout16 + (size_t)node * H + lane * 8) = outw;
}

// ---------------- mean over nodes (fp16 input, fp32 accumulate) ----------------
__global__ void mean_kernel(const __half* __restrict__ h, float* __restrict__ mean, int n) {
    float acc = 0.0f;
    for (int r = blockIdx.x; r < n; r += gridDim.x)
        acc += __half2float(h[(size_t)r * H + threadIdx.x]);
    atomicAdd(&mean[threadIdx.x], acc);
}

// ---------------- head MLP ----------------
__global__ void head_kernel(const float* __restrict__ mean,
                            const float* __restrict__ W1, const float* __restrict__ b1,
                            const float* __restrict__ W2, const float* __restrict__ b2,
                            float* __restrict__ out, float invN)
{
    __shared__ float g[H];
    __shared__ float t[D_OUT];
    int tid = threadIdx.x;  // 128 threads
    g[tid]       = mean[tid]       * invN;
    g[tid + 128] = mean[tid + 128] * invN;
    __syncthreads();
    float acc = b1[tid];
    for (int k = 0; k < H; k++) acc = fmaf(g[k], W1[k * D_OUT + tid], acc);
    t[tid] = fmaxf(acc, 0.0f);
    __syncthreads();
    float acc2 = b2[tid];
    for (int k = 0; k < D_OUT; k++) acc2 = fmaf(t[k], W2[k * D_OUT + tid], acc2);
    out[tid] = acc2;
}

// ---------------- launch ----------------
extern "C" void kernel_launch(void* const* d_in, const int* in_sizes, int n_in,
                              void* d_out, int out_size)
{
    const float* x       = (const float*)d_in[0];
    const int*   eidx    = (const int*)  d_in[1];
    const float* W_enc1  = (const float*)d_in[3];
    const float* b_enc1  = (const float*)d_in[4];
    const float* W_enc2  = (const float*)d_in[5];
    const float* b_enc2  = (const float*)d_in[6];
    const float* W_g[3]  = { (const float*)d_in[8],  (const float*)d_in[10], (const float*)d_in[12] };
    const float* b_g[3]  = { (const float*)d_in[9],  (const float*)d_in[11], (const float*)d_in[13] };
    const float* W_h1    = (const float*)d_in[14];
    const float* b_h1    = (const float*)d_in[15];
    const float* W_h2    = (const float*)d_in[16];
    const float* b_h2    = (const float*)d_in[17];

    const int n = in_sizes[0] / D_IN;       // 50000
    const int E = in_sizes[2];              // 1600000
    const int* src = eidx;
    const int* dst = eidx + E;

    __half *p_h16, *p_hw16, *p_w16;
    float *p_dis, *p_mean;
    int *p_deg, *p_start, *p_cursor, *p_csr, *p_bsum, *p_boff;
    cudaGetSymbolAddress((void**)&p_h16,    g_h16);
    cudaGetSymbolAddress((void**)&p_hw16,   g_hw16);
    cudaGetSymbolAddress((void**)&p_w16,    g_w16);
    cudaGetSymbolAddress((void**)&p_dis,    g_dis);
    cudaGetSymbolAddress((void**)&p_deg,    g_deg);
    cudaGetSymbolAddress((void**)&p_start,  g_start);
    cudaGetSymbolAddress((void**)&p_cursor, g_cursor);
    cudaGetSymbolAddress((void**)&p_csr,    g_csr_src);
    cudaGetSymbolAddress((void**)&p_bsum,   g_bsum);
    cudaGetSymbolAddress((void**)&p_boff,   g_boff);
    cudaGetSymbolAddress((void**)&p_mean,   g_mean);

    // 0) convert the four H x H weights to transposed fp16
    const float* wsrc[4] = { W_enc2, W_g[0], W_g[1], W_g[2] };
    for (int i = 0; i < 4; ++i)
        wtrans_kernel<<<(H * H + 255) / 256, 256>>>(wsrc[i], p_w16 + (size_t)i * H * H, H, H);

    // 1) degrees, norm, CSR build
    cudaMemsetAsync(p_deg, 0, n * sizeof(int), 0);
    deg_kernel<<<(E + 255) / 256, 256>>>(dst, p_deg, E);
    dis_kernel<<<(n + 255) / 256, 256>>>(p_deg, p_dis, n);
    const int nScanBlocks = (n + 1023) / 1024;
    scan_block_kernel<<<nScanBlocks, 1024>>>(p_deg, p_start, p_bsum, n);
    scan_sums_kernel<<<1, 64>>>(p_bsum, p_boff, nScanBlocks);
    scan_finalize_kernel<<<(n + 255) / 256, 256>>>(p_deg, p_start, p_boff, p_cursor, n);
    fill_csr_kernel<<<(E + 255) / 256, 256>>>(src, dst, p_cursor, p_csr, E);

    dim3 gemmBlock(256);
    dim3 gemmGrid(H / 128, (n + 127) / 128);

    // 2) encoder L1 (fp32 x, tf32 mma) -> fp16 mirror only
    tf32_gemm_kernel<<<gemmGrid, gemmBlock>>>(x, W_enc1, b_enc1, nullptr, p_hw16, n, D_IN, H, 1);
    // encoder L2 (fp16)
    fp16_gemm_kernel<<<gemmGrid, gemmBlock>>>(p_hw16, p_w16 + 0 * H * H, b_enc2, p_h16, n, H, H, 0);

    // 3) three GCN layers
    const int warpsPerBlock = 256 / 32;
    const int gatherBlocks = (n + warpsPerBlock - 1) / warpsPerBlock;
    for (int l = 0; l < 3; ++l) {
        fp16_gemm_kernel<<<gemmGrid, gemmBlock>>>(p_h16, p_w16 + (size_t)(l + 1) * H * H,
                                                  nullptr, p_hw16, n, H, H, 0);
        gather_kernel<<<gatherBlocks, 256>>>(p_hw16, p_dis, b_g[l], p_start, p_csr, p_h16, n);
    }

    // 4) mean pooling + head
    cudaMemsetAsync(p_mean, 0, H * sizeof(float), 0);
    mean_kernel<<<128, H>>>(p_h16, p_mean, n);
    head_kernel<<<1, D_OUT>>>(p_mean, W_h1, b_h1, W_h2, b_h2, (float*)d_out, 1.0f / (float)n);
}

// round 6
// speedup vs baseline: 7.2556x; 1.0374x over previous
#include <cuda_runtime.h>
#include <cuda_fp16.h>
#include <cuda_bf16.h>
#include <cstdint>

#define NODES_MAX 50000
#define EDGES_MAX 1600000
#define H 256
#define D_IN 518
#define D_INP 544          // D_IN padded to multiple of 32
#define D_OUT 128

// ---------------- device scratch ----------------
__device__ __half g_x16 [NODES_MAX * D_INP];              // padded fp16 input
__device__ __half g_h16 [NODES_MAX * H];                  // layer activations
__device__ __half g_hw16[NODES_MAX * H];                  // GEMM outputs
__device__ __half g_w16 [H * D_INP + 4 * H * H];          // fp16 transposed weights
__device__ float  g_dis[NODES_MAX];
__device__ int    g_deg[NODES_MAX];
__device__ int    g_start[NODES_MAX + 1];
__device__ int    g_cursor[NODES_MAX];
__device__ int    g_csr_src[EDGES_MAX];
__device__ int    g_bsum[64];
__device__ int    g_boff[64];
__device__ float  g_mean[H];

// ---------------- input conversion: x fp32 [N,518] -> fp16 [N,544] zero-padded ----------------
__global__ void xconv_kernel(const float* __restrict__ x, __half* __restrict__ x16, int n) {
    int idx = blockIdx.x * blockDim.x + threadIdx.x;
    if (idx >= n * D_INP) return;
    int row = idx / D_INP, col = idx % D_INP;
    float v = (col < D_IN) ? x[(size_t)row * D_IN + col] : 0.0f;
    x16[idx] = __float2half_rn(v);
}

// ---------------- weight transpose + fp16: WT[m][k] = W[k][m], k zero-padded to Kp ----------------
__global__ void wtrans_kernel(const float* __restrict__ W, __half* __restrict__ WT,
                              int K, int M, int Kp) {
    int idx = blockIdx.x * blockDim.x + threadIdx.x;
    if (idx >= M * Kp) return;
    int m = idx / Kp, k = idx % Kp;
    float v = (k < K) ? W[(size_t)k * M + m] : 0.0f;
    WT[idx] = __float2half_rn(v);
}

// ---------------- degree / normalization ----------------
__global__ void deg_kernel(const int* __restrict__ dst, int* __restrict__ deg, int E) {
    int i = blockIdx.x * blockDim.x + threadIdx.x;
    if (i < E) atomicAdd(&deg[dst[i]], 1);
}

__global__ void dis_kernel(const int* __restrict__ deg, float* __restrict__ dis, int n) {
    int i = blockIdx.x * blockDim.x + threadIdx.x;
    if (i < n) dis[i] = rsqrtf(1.0f + (float)deg[i]);
}

// ---------------- parallel scan (3 phases) ----------------
__global__ void scan_block_kernel(const int* __restrict__ deg, int* __restrict__ start,
                                  int* __restrict__ bsum, int n)
{
    __shared__ int warpSums[32];
    int i = blockIdx.x * 1024 + threadIdx.x;
    int lane = threadIdx.x & 31, warp = threadIdx.x >> 5;
    int v = (i < n) ? deg[i] : 0;
    int inc = v;
#pragma unroll
    for (int off = 1; off < 32; off <<= 1) {
        int t = __shfl_up_sync(0xffffffff, inc, off);
        if (lane >= off) inc += t;
    }
    if (lane == 31) warpSums[warp] = inc;
    __syncthreads();
    if (warp == 0) {
        int s = warpSums[lane];
#pragma unroll
        for (int off = 1; off < 32; off <<= 1) {
            int t = __shfl_up_sync(0xffffffff, s, off);
            if (lane >= off) s += t;
        }
        warpSums[lane] = s;
    }
    __syncthreads();
    int add = (warp > 0) ? warpSums[warp - 1] : 0;
    inc += add;
    if (i < n) start[i + 1] = inc;
    if (threadIdx.x == 1023) bsum[blockIdx.x] = inc;
}

__global__ void scan_sums_kernel(const int* __restrict__ bsum, int* __restrict__ boff, int nb) {
    int lane = threadIdx.x;  // 64 threads
    int v = (lane < nb) ? bsum[lane] : 0;
    __shared__ int s[64];
    s[lane] = v;
    __syncthreads();
    for (int off = 1; off < 64; off <<= 1) {
        int t = (lane >= off) ? s[lane - off] : 0;
        __syncthreads();
        s[lane] += t;
        __syncthreads();
    }
    if (lane < nb) boff[lane] = (lane > 0) ? s[lane - 1] : 0;
}

__global__ void scan_finalize_kernel(const int* __restrict__ deg, int* __restrict__ start,
                                     const int* __restrict__ boff, int* __restrict__ cursor, int n)
{
    int i = blockIdx.x * blockDim.x + threadIdx.x;
    if (i < n) {
        int s = start[i + 1] + boff[i >> 10];
        start[i + 1] = s;
        cursor[i] = s - deg[i];
        if (i == 0) start[0] = 0;
    }
}

// ---------------- bucket edges by dst ----------------
__global__ void fill_csr_kernel(const int* __restrict__ src, const int* __restrict__ dst,
                                int* __restrict__ cursor, int* __restrict__ csr_src, int E)
{
    int e = blockIdx.x * blockDim.x + threadIdx.x;
    if (e < E) {
        int d = dst[e];
        int p = atomicAdd(&cursor[d], 1);
        csr_src[p] = src[e];
    }
}

// ---------------- fp16 tensor-core GEMM, BK=32, cp.async double-buffered ----------------
// C16[N,M] = A16[N,K] @ BT16[M,K]^T (+bias)(+relu), fp32 accumulate. K multiple of 32.
__global__ __launch_bounds__(256)
void fp16_gemm_kernel(const __half* __restrict__ A, const __half* __restrict__ BT,
                      const float* __restrict__ bias, __half* __restrict__ C16,
                      int N, int K, int M, int doRelu)
{
    const int BM = 128, BN = 128, BK = 32, PAD = 40;  // 40 halves = 80B row stride
    __shared__ alignas(16) __half Ah[2][BM][PAD];     // Ah[buf][m][k]
    __shared__ alignas(16) __half Bh[2][BN][PAD];     // Bh[buf][n][k]

    int tid = threadIdx.x;
    int wid = tid >> 5, lane = tid & 31;
    int warp_m = (wid & 1) * 64;
    int warp_n = (wid >> 1) * 32;
    int lq = lane & 3;
    int lg = lane >> 2;

    int row0 = blockIdx.y * BM;
    int col0 = blockIdx.x * BN;
    int nt = K / BK;

    float c[4][4][4];
#pragma unroll
    for (int mi = 0; mi < 4; mi++)
#pragma unroll
        for (int ni = 0; ni < 4; ni++)
#pragma unroll
            for (int r = 0; r < 4; r++) c[mi][ni][r] = 0.0f;

    auto loadTile = [&](int t, int buf) {
        int k0 = t * BK;
#pragma unroll
        for (int it = 0; it < 2; ++it) {
            int chunk = it * 256 + tid;          // 512 chunks of 16B per matrix
            int r = chunk >> 2, c8 = (chunk & 3) * 8;
            {
                int gm = row0 + r;
                const __half* src = A + (size_t)gm * K + k0 + c8;
                uint32_t dsh = (uint32_t)__cvta_generic_to_shared(&Ah[buf][r][c8]);
                int sz = (gm < N) ? 16 : 0;
                asm volatile("cp.async.cg.shared.global [%0], [%1], 16, %2;"
                             :: "r"(dsh), "l"(src), "r"(sz));
            }
            {
                int gn = col0 + r;               // always < M
                const __half* src = BT + (size_t)gn * K + k0 + c8;
                uint32_t dsh = (uint32_t)__cvta_generic_to_shared(&Bh[buf][r][c8]);
                asm volatile("cp.async.cg.shared.global [%0], [%1], 16;"
                             :: "r"(dsh), "l"(src));
            }
        }
        asm volatile("cp.async.commit_group;");
    };

    loadTile(0, 0);
    for (int t = 0; t < nt; ++t) {
        int buf = t & 1;
        if (t + 1 < nt) {
            loadTile(t + 1, (t + 1) & 1);
            asm volatile("cp.async.wait_group 1;");
        } else {
            asm volatile("cp.async.wait_group 0;");
        }
        __syncthreads();

#pragma unroll
        for (int kk = 0; kk < BK; kk += 16) {
            int kc = kk + lq * 2;
            uint32_t af[4][4], bf[4][2];
#pragma unroll
            for (int mi = 0; mi < 4; mi++) {
                int mrow = warp_m + mi * 16 + lg;
                af[mi][0] = *reinterpret_cast<const uint32_t*>(&Ah[buf][mrow    ][kc    ]);
                af[mi][1] = *reinterpret_cast<const uint32_t*>(&Ah[buf][mrow + 8][kc    ]);
                af[mi][2] = *reinterpret_cast<const uint32_t*>(&Ah[buf][mrow    ][kc + 8]);
                af[mi][3] = *reinterpret_cast<const uint32_t*>(&Ah[buf][mrow + 8][kc + 8]);
            }
#pragma unroll
            for (int ni = 0; ni < 4; ni++) {
                int ncol = warp_n + ni * 8 + lg;
                bf[ni][0] = *reinterpret_cast<const uint32_t*>(&Bh[buf][ncol][kc    ]);
                bf[ni][1] = *reinterpret_cast<const uint32_t*>(&Bh[buf][ncol][kc + 8]);
            }
#pragma unroll
            for (int mi = 0; mi < 4; mi++)
#pragma unroll
                for (int ni = 0; ni < 4; ni++) {
                    asm volatile(
                        "mma.sync.aligned.m16n8k16.row.col.f32.f16.f16.f32 "
                        "{%0,%1,%2,%3}, {%4,%5,%6,%7}, {%8,%9}, {%0,%1,%2,%3};"
                        : "+f"(c[mi][ni][0]), "+f"(c[mi][ni][1]),
                          "+f"(c[mi][ni][2]), "+f"(c[mi][ni][3])
                        : "r"(af[mi][0]), "r"(af[mi][1]), "r"(af[mi][2]), "r"(af[mi][3]),
                          "r"(bf[ni][0]), "r"(bf[ni][1]));
                }
        }
        __syncthreads();
    }

#pragma unroll
    for (int mi = 0; mi < 4; mi++) {
#pragma unroll
        for (int ni = 0; ni < 4; ni++) {
            int r = row0 + warp_m + mi * 16 + lg;
            int cc = col0 + warp_n + ni * 8 + lq * 2;
            float v0 = c[mi][ni][0], v1 = c[mi][ni][1];
            float v2 = c[mi][ni][2], v3 = c[mi][ni][3];
            if (bias) {
                float bA = bias[cc], bB = bias[cc + 1];
                v0 += bA; v1 += bB; v2 += bA; v3 += bB;
            }
            if (doRelu) {
                v0 = fmaxf(v0, 0.f); v1 = fmaxf(v1, 0.f);
                v2 = fmaxf(v2, 0.f); v3 = fmaxf(v3, 0.f);
            }
            if (r < N)
                *reinterpret_cast<__half2*>(C16 + (size_t)r * M + cc) = __floats2half2_rn(v0, v1);
            if (r + 8 < N)
                *reinterpret_cast<__half2*>(C16 + (size_t)(r + 8) * M + cc) = __floats2half2_rn(v2, v3);
        }
    }
}

// ---------------- fused GCN aggregation: fp16 rows, fp32 accumulate, fp16 out ----------------
__device__ __forceinline__ void accum_row(const __half2* hp, float w, float4& a0, float4& a1) {
    float2 f0 = __half22float2(hp[0]), f1 = __half22float2(hp[1]);
    float2 f2 = __half22float2(hp[2]), f3 = __half22float2(hp[3]);
    a0.x = fmaf(f0.x, w, a0.x); a0.y = fmaf(f0.y, w, a0.y);
    a0.z = fmaf(f1.x, w, a0.z); a0.w = fmaf(f1.y, w, a0.w);
    a1.x = fmaf(f2.x, w, a1.x); a1.y = fmaf(f2.y, w, a1.y);
    a1.z = fmaf(f3.x, w, a1.z); a1.w = fmaf(f3.y, w, a1.w);
}

__global__ __launch_bounds__(256)
void gather_kernel(const __half* __restrict__ hw16,
                   const float* __restrict__ dis, const float* __restrict__ b,
                   const int* __restrict__ start, const int* __restrict__ csr_src,
                   __half* __restrict__ hout16, int n)
{
    int warp = (blockIdx.x * blockDim.x + threadIdx.x) >> 5;
    if (warp >= n) return;
    int lane = threadIdx.x & 31;
    int node = warp;

    float dd = dis[node];
    float self = dd * dd;

    uint4 us = *reinterpret_cast<const uint4*>(hw16 + (size_t)node * H + lane * 8);
    const __half2* hs = reinterpret_cast<const __half2*>(&us);
    const float4* bb = reinterpret_cast<const float4*>(b);
    float4 b0 = bb[lane * 2 + 0];
    float4 b1 = bb[lane * 2 + 1];
    float2 s0 = __half22float2(hs[0]), s1 = __half22float2(hs[1]);
    float2 s2 = __half22float2(hs[2]), s3 = __half22float2(hs[3]);

    float4 a0, a1;
    a0.x = fmaf(s0.x, self, b0.x); a0.y = fmaf(s0.y, self, b0.y);
    a0.z = fmaf(s1.x, self, b0.z); a0.w = fmaf(s1.y, self, b0.w);
    a1.x = fmaf(s2.x, self, b1.x); a1.y = fmaf(s2.y, self, b1.y);
    a1.z = fmaf(s3.x, self, b1.z); a1.w = fmaf(s3.y, self, b1.w);

    int j0 = start[node], j1 = start[node + 1];

    int j = j0;
    for (; j + 4 <= j1; j += 4) {
        int sA = csr_src[j], sB = csr_src[j + 1], sC = csr_src[j + 2], sD = csr_src[j + 3];
        float wA = dis[sA] * dd, wB = dis[sB] * dd, wC = dis[sC] * dd, wD = dis[sD] * dd;
        uint4 uA = *reinterpret_cast<const uint4*>(hw16 + (size_t)sA * H + lane * 8);
        uint4 uB = *reinterpret_cast<const uint4*>(hw16 + (size_t)sB * H + lane * 8);
        uint4 uC = *reinterpret_cast<const uint4*>(hw16 + (size_t)sC * H + lane * 8);
        uint4 uD = *reinterpret_cast<const uint4*>(hw16 + (size_t)sD * H + lane * 8);
        accum_row(reinterpret_cast<const __half2*>(&uA), wA, a0, a1);
        accum_row(reinterpret_cast<const __half2*>(&uB), wB, a0, a1);
        accum_row(reinterpret_cast<const __half2*>(&uC), wC, a0, a1);
        accum_row(reinterpret_cast<const __half2*>(&uD), wD, a0, a1);
    }
    for (; j < j1; ++j) {
        int s = csr_src[j];
        float w = dis[s] * dd;
        uint4 u = *reinterpret_cast<const uint4*>(hw16 + (size_t)s * H + lane * 8);
        accum_row(reinterpret_cast<const __half2*>(&u), w, a0, a1);
    }

    a0.x = fmaxf(a0.x, 0.f); a0.y = fmaxf(a0.y, 0.f);
    a0.z = fmaxf(a0.z, 0.f); a0.w = fmaxf(a0.w, 0.f);
    a1.x = fmaxf(a1.x, 0.f); a1.y = fmaxf(a1.y, 0.f);
    a1.z = fmaxf(a1.z, 0.f); a1.w = fmaxf(a1.w, 0.f);

    uint4 outw;
    __half2* ho = reinterpret_cast<__half2*>(&outw);
    ho[0] = __floats2half2_rn(a0.x, a0.y);
    ho[1] = __floats2half2_rn(a0.z, a0.w);
    ho[2] = __floats2half2_rn(a1.x, a1.y);
    ho[3] = __floats2half2_rn(a1.z, a1.w);
    *reinterpret_cast<uint4*>(hout16 + (size_t)node * H + lane * 8) = outw;
}

// ---------------- mean over nodes ----------------
__global__ void mean_kernel(const __half* __restrict__ h, float* __restrict__ mean, int n) {
    float acc = 0.0f;
    for (int r = blockIdx.x; r < n; r += gridDim.x)
        acc += __half2float(h[(size_t)r * H + threadIdx.x]);
    atomicAdd(&mean[threadIdx.x], acc);
}

// ---------------- head MLP ----------------
__global__ void head_kernel(const float* __restrict__ mean,
                            const float* __restrict__ W1, const float* __restrict__ b1,
                            const float* __restrict__ W2, const float* __restrict__ b2,
                            float* __restrict__ out, float invN)
{
    __shared__ float g[H];
    __shared__ float t[D_OUT];
    int tid = threadIdx.x;  // 128 threads
    g[tid]       = mean[tid]       * invN;
    g[tid + 128] = mean[tid + 128] * invN;
    __syncthreads();
    float acc = b1[tid];
    for (int k = 0; k < H; k++) acc = fmaf(g[k], W1[k * D_OUT + tid], acc);
    t[tid] = fmaxf(acc, 0.0f);
    __syncthreads();
    float acc2 = b2[tid];
    for (int k = 0; k < D_OUT; k++) acc2 = fmaf(t[k], W2[k * D_OUT + tid], acc2);
    out[tid] = acc2;
}

// ---------------- launch ----------------
extern "C" void kernel_launch(void* const* d_in, const int* in_sizes, int n_in,
                              void* d_out, int out_size)
{
    const float* x       = (const float*)d_in[0];
    const int*   eidx    = (const int*)  d_in[1];
    const float* W_enc1  = (const float*)d_in[3];
    const float* b_enc1  = (const float*)d_in[4];
    const float* W_enc2  = (const float*)d_in[5];
    const float* b_enc2  = (const float*)d_in[6];
    const float* W_g[3]  = { (const float*)d_in[8],  (const float*)d_in[10], (const float*)d_in[12] };
    const float* b_g[3]  = { (const float*)d_in[9],  (const float*)d_in[11], (const float*)d_in[13] };
    const float* W_h1    = (const float*)d_in[14];
    const float* b_h1    = (const float*)d_in[15];
    const float* W_h2    = (const float*)d_in[16];
    const float* b_h2    = (const float*)d_in[17];

    const int n = in_sizes[0] / D_IN;       // 50000
    const int E = in_sizes[2];              // 1600000
    const int* src = eidx;
    const int* dst = eidx + E;

    __half *p_x16, *p_h16, *p_hw16, *p_w16;
    float *p_dis, *p_mean;
    int *p_deg, *p_start, *p_cursor, *p_csr, *p_bsum, *p_boff;
    cudaGetSymbolAddress((void**)&p_x16,    g_x16);
    cudaGetSymbolAddress((void**)&p_h16,    g_h16);
    cudaGetSymbolAddress((void**)&p_hw16,   g_hw16);
    cudaGetSymbolAddress((void**)&p_w16,    g_w16);
    cudaGetSymbolAddress((void**)&p_dis,    g_dis);
    cudaGetSymbolAddress((void**)&p_deg,    g_deg);
    cudaGetSymbolAddress((void**)&p_start,  g_start);
    cudaGetSymbolAddress((void**)&p_cursor, g_cursor);
    cudaGetSymbolAddress((void**)&p_csr,    g_csr_src);
    cudaGetSymbolAddress((void**)&p_bsum,   g_bsum);
    cudaGetSymbolAddress((void**)&p_boff,   g_boff);
    cudaGetSymbolAddress((void**)&p_mean,   g_mean);

    __half* WT_enc1 = p_w16;                         // [H][D_INP]
    __half* WT_sq   = p_w16 + (size_t)H * D_INP;     // 4 x [H][H]: enc2, g1, g2, g3

    // 0) weight + input conversion
    wtrans_kernel<<<(H * D_INP + 255) / 256, 256>>>(W_enc1, WT_enc1, D_IN, H, D_INP);
    const float* wsrc[4] = { W_enc2, W_g[0], W_g[1], W_g[2] };
    for (int i = 0; i < 4; ++i)
        wtrans_kernel<<<(H * H + 255) / 256, 256>>>(wsrc[i], WT_sq + (size_t)i * H * H, H, H, H);
    xconv_kernel<<<(n * D_INP + 255) / 256, 256>>>(x, p_x16, n);

    // 1) degrees, norm, CSR build
    cudaMemsetAsync(p_deg, 0, n * sizeof(int), 0);
    deg_kernel<<<(E + 255) / 256, 256>>>(dst, p_deg, E);
    dis_kernel<<<(n + 255) / 256, 256>>>(p_deg, p_dis, n);
    const int nScanBlocks = (n + 1023) / 1024;
    scan_block_kernel<<<nScanBlocks, 1024>>>(p_deg, p_start, p_bsum, n);
    scan_sums_kernel<<<1, 64>>>(p_bsum, p_boff, nScanBlocks);
    scan_finalize_kernel<<<(n + 255) / 256, 256>>>(p_deg, p_start, p_boff, p_cursor, n);
    fill_csr_kernel<<<(E + 255) / 256, 256>>>(src, dst, p_cursor, p_csr, E);

    dim3 gemmBlock(256);
    dim3 gemmGrid(H / 128, (n + 127) / 128);

    // 2) encoder (both fp16)
    fp16_gemm_kernel<<<gemmGrid, gemmBlock>>>(p_x16,  WT_enc1,          b_enc1, p_hw16, n, D_INP, H, 1);
    fp16_gemm_kernel<<<gemmGrid, gemmBlock>>>(p_hw16, WT_sq + 0 * H * H, b_enc2, p_h16,  n, H,     H, 0);

    // 3) three GCN layers
    const int warpsPerBlock = 256 / 32;
    const int gatherBlocks = (n + warpsPerBlock - 1) / warpsPerBlock;
    for (int l = 0; l < 3; ++l) {
        fp16_gemm_kernel<<<gemmGrid, gemmBlock>>>(p_h16, WT_sq + (size_t)(l + 1) * H * H,
                                                  nullptr, p_hw16, n, H, H, 0);
        gather_kernel<<<gatherBlocks, 256>>>(p_hw16, p_dis, b_g[l], p_start, p_csr, p_h16, n);
    }

    // 4) mean pooling + head
    cudaMemsetAsync(p_mean, 0, H * sizeof(float), 0);
    mean_kernel<<<128, H>>>(p_h16, p_mean, n);
    head_kernel<<<1, D_OUT>>>(p_mean, W_h1, b_h1, W_h2, b_h2, (float*)d_out, 1.0f / (float)n);
}

// round 7
// speedup vs baseline: 8.4860x; 1.1696x over previous
#include <cuda_runtime.h>
#include <cuda_fp16.h>
#include <cuda_bf16.h>
#include <cstdint>

#define NODES_MAX 50000
#define EDGES_MAX 1600000
#define H 256
#define D_IN 518
#define D_INP 544          // D_IN padded to multiple of 32
#define D_OUT 128

// ---------------- device scratch ----------------
__device__ __half g_x16 [NODES_MAX * D_INP];
__device__ __half g_h16 [NODES_MAX * H];
__device__ __half g_hw16[NODES_MAX * H];
__device__ __half g_w16 [H * D_INP + 4 * H * H];
__device__ float  g_dis[NODES_MAX];
__device__ int    g_deg[NODES_MAX];
__device__ int    g_start[NODES_MAX + 1];
__device__ int    g_cursor[NODES_MAX];
__device__ int    g_csr_src[EDGES_MAX];
__device__ int    g_bsum[64];
__device__ int    g_boff[64];
__device__ float  g_mean[H];

// ---------------- input conversion ----------------
__global__ void xconv_kernel(const float* __restrict__ x, __half* __restrict__ x16, int n) {
    int idx = blockIdx.x * blockDim.x + threadIdx.x;
    if (idx >= n * D_INP) return;
    int row = idx / D_INP, col = idx % D_INP;
    float v = (col < D_IN) ? x[(size_t)row * D_IN + col] : 0.0f;
    x16[idx] = __float2half_rn(v);
}

__global__ void wtrans_kernel(const float* __restrict__ W, __half* __restrict__ WT,
                              int K, int M, int Kp) {
    int idx = blockIdx.x * blockDim.x + threadIdx.x;
    if (idx >= M * Kp) return;
    int m = idx / Kp, k = idx % Kp;
    float v = (k < K) ? W[(size_t)k * M + m] : 0.0f;
    WT[idx] = __float2half_rn(v);
}

// ---------------- degree / normalization ----------------
__global__ void deg_kernel(const int* __restrict__ dst, int* __restrict__ deg, int E) {
    int i = blockIdx.x * blockDim.x + threadIdx.x;
    if (i < E) atomicAdd(&deg[dst[i]], 1);
}

__global__ void dis_kernel(const int* __restrict__ deg, float* __restrict__ dis, int n) {
    int i = blockIdx.x * blockDim.x + threadIdx.x;
    if (i < n) dis[i] = rsqrtf(1.0f + (float)deg[i]);
}

// ---------------- parallel scan (3 phases) ----------------
__global__ void scan_block_kernel(const int* __restrict__ deg, int* __restrict__ start,
                                  int* __restrict__ bsum, int n)
{
    __shared__ int warpSums[32];
    int i = blockIdx.x * 1024 + threadIdx.x;
    int lane = threadIdx.x & 31, warp = threadIdx.x >> 5;
    int v = (i < n) ? deg[i] : 0;
    int inc = v;
#pragma unroll
    for (int off = 1; off < 32; off <<= 1) {
        int t = __shfl_up_sync(0xffffffff, inc, off);
        if (lane >= off) inc += t;
    }
    if (lane == 31) warpSums[warp] = inc;
    __syncthreads();
    if (warp == 0) {
        int s = warpSums[lane];
#pragma unroll
        for (int off = 1; off < 32; off <<= 1) {
            int t = __shfl_up_sync(0xffffffff, s, off);
            if (lane >= off) s += t;
        }
        warpSums[lane] = s;
    }
    __syncthreads();
    int add = (warp > 0) ? warpSums[warp - 1] : 0;
    inc += add;
    if (i < n) start[i + 1] = inc;
    if (threadIdx.x == 1023) bsum[blockIdx.x] = inc;
}

__global__ void scan_sums_kernel(const int* __restrict__ bsum, int* __restrict__ boff, int nb) {
    int lane = threadIdx.x;  // 64 threads
    int v = (lane < nb) ? bsum[lane] : 0;
    __shared__ int s[64];
    s[lane] = v;
    __syncthreads();
    for (int off = 1; off < 64; off <<= 1) {
        int t = (lane >= off) ? s[lane - off] : 0;
        __syncthreads();
        s[lane] += t;
        __syncthreads();
    }
    if (lane < nb) boff[lane] = (lane > 0) ? s[lane - 1] : 0;
}

__global__ void scan_finalize_kernel(const int* __restrict__ deg, int* __restrict__ start,
                                     const int* __restrict__ boff, int* __restrict__ cursor, int n)
{
    int i = blockIdx.x * blockDim.x + threadIdx.x;
    if (i < n) {
        int s = start[i + 1] + boff[i >> 10];
        start[i + 1] = s;
        cursor[i] = s - deg[i];
        if (i == 0) start[0] = 0;
    }
}

__global__ void fill_csr_kernel(const int* __restrict__ src, const int* __restrict__ dst,
                                int* __restrict__ cursor, int* __restrict__ csr_src, int E)
{
    int e = blockIdx.x * blockDim.x + threadIdx.x;
    if (e < E) {
        int d = dst[e];
        int p = atomicAdd(&cursor[d], 1);
        csr_src[p] = src[e];
    }
}

// ---------------- fp16 tensor-core GEMM, BK=32, cp.async double-buffered ----------------
__global__ __launch_bounds__(256)
void fp16_gemm_kernel(const __half* __restrict__ A, const __half* __restrict__ BT,
                      const float* __restrict__ bias, __half* __restrict__ C16,
                      int N, int K, int M, int doRelu)
{
    const int BM = 128, BN = 128, BK = 32, PAD = 40;
    __shared__ alignas(16) __half Ah[2][BM][PAD];
    __shared__ alignas(16) __half Bh[2][BN][PAD];

    int tid = threadIdx.x;
    int wid = tid >> 5, lane = tid & 31;
    int warp_m = (wid & 1) * 64;
    int warp_n = (wid >> 1) * 32;
    int lq = lane & 3;
    int lg = lane >> 2;

    int row0 = blockIdx.y * BM;
    int col0 = blockIdx.x * BN;
    int nt = K / BK;

    float c[4][4][4];
#pragma unroll
    for (int mi = 0; mi < 4; mi++)
#pragma unroll
        for (int ni = 0; ni < 4; ni++)
#pragma unroll
            for (int r = 0; r < 4; r++) c[mi][ni][r] = 0.0f;

    auto loadTile = [&](int t, int buf) {
        int k0 = t * BK;
#pragma unroll
        for (int it = 0; it < 2; ++it) {
            int chunk = it * 256 + tid;
            int r = chunk >> 2, c8 = (chunk & 3) * 8;
            {
                int gm = row0 + r;
                const __half* src = A + (size_t)gm * K + k0 + c8;
                uint32_t dsh = (uint32_t)__cvta_generic_to_shared(&Ah[buf][r][c8]);
                int sz = (gm < N) ? 16 : 0;
                asm volatile("cp.async.cg.shared.global [%0], [%1], 16, %2;"
                             :: "r"(dsh), "l"(src), "r"(sz));
            }
            {
                int gn = col0 + r;
                const __half* src = BT + (size_t)gn * K + k0 + c8;
                uint32_t dsh = (uint32_t)__cvta_generic_to_shared(&Bh[buf][r][c8]);
                asm volatile("cp.async.cg.shared.global [%0], [%1], 16;"
                             :: "r"(dsh), "l"(src));
            }
        }
        asm volatile("cp.async.commit_group;");
    };

    loadTile(0, 0);
    for (int t = 0; t < nt; ++t) {
        int buf = t & 1;
        if (t + 1 < nt) {
            loadTile(t + 1, (t + 1) & 1);
            asm volatile("cp.async.wait_group 1;");
        } else {
            asm volatile("cp.async.wait_group 0;");
        }
        __syncthreads();

#pragma unroll
        for (int kk = 0; kk < BK; kk += 16) {
            int kc = kk + lq * 2;
            uint32_t af[4][4], bf[4][2];
#pragma unroll
            for (int mi = 0; mi < 4; mi++) {
                int mrow = warp_m + mi * 16 + lg;
                af[mi][0] = *reinterpret_cast<const uint32_t*>(&Ah[buf][mrow    ][kc    ]);
                af[mi][1] = *reinterpret_cast<const uint32_t*>(&Ah[buf][mrow + 8][kc    ]);
                af[mi][2] = *reinterpret_cast<const uint32_t*>(&Ah[buf][mrow    ][kc + 8]);
                af[mi][3] = *reinterpret_cast<const uint32_t*>(&Ah[buf][mrow + 8][kc + 8]);
            }
#pragma unroll
            for (int ni = 0; ni < 4; ni++) {
                int ncol = warp_n + ni * 8 + lg;
                bf[ni][0] = *reinterpret_cast<const uint32_t*>(&Bh[buf][ncol][kc    ]);
                bf[ni][1] = *reinterpret_cast<const uint32_t*>(&Bh[buf][ncol][kc + 8]);
            }
#pragma unroll
            for (int mi = 0; mi < 4; mi++)
#pragma unroll
                for (int ni = 0; ni < 4; ni++) {
                    asm volatile(
                        "mma.sync.aligned.m16n8k16.row.col.f32.f16.f16.f32 "
                        "{%0,%1,%2,%3}, {%4,%5,%6,%7}, {%8,%9}, {%0,%1,%2,%3};"
                        : "+f"(c[mi][ni][0]), "+f"(c[mi][ni][1]),
                          "+f"(c[mi][ni][2]), "+f"(c[mi][ni][3])
                        : "r"(af[mi][0]), "r"(af[mi][1]), "r"(af[mi][2]), "r"(af[mi][3]),
                          "r"(bf[ni][0]), "r"(bf[ni][1]));
                }
        }
        __syncthreads();
    }

#pragma unroll
    for (int mi = 0; mi < 4; mi++) {
#pragma unroll
        for (int ni = 0; ni < 4; ni++) {
            int r = row0 + warp_m + mi * 16 + lg;
            int cc = col0 + warp_n + ni * 8 + lq * 2;
            float v0 = c[mi][ni][0], v1 = c[mi][ni][1];
            float v2 = c[mi][ni][2], v3 = c[mi][ni][3];
            if (bias) {
                float bA = bias[cc], bB = bias[cc + 1];
                v0 += bA; v1 += bB; v2 += bA; v3 += bB;
            }
            if (doRelu) {
                v0 = fmaxf(v0, 0.f); v1 = fmaxf(v1, 0.f);
                v2 = fmaxf(v2, 0.f); v3 = fmaxf(v3, 0.f);
            }
            if (r < N)
                *reinterpret_cast<__half2*>(C16 + (size_t)r * M + cc) = __floats2half2_rn(v0, v1);
            if (r + 8 < N)
                *reinterpret_cast<__half2*>(C16 + (size_t)(r + 8) * M + cc) = __floats2half2_rn(v2, v3);
        }
    }
}

// ---------------- fused GCN aggregation (+ optional mean accumulation) ----------------
__device__ __forceinline__ void accum_row(const __half2* hp, float w, float4& a0, float4& a1) {
    float2 f0 = __half22float2(hp[0]), f1 = __half22float2(hp[1]);
    float2 f2 = __half22float2(hp[2]), f3 = __half22float2(hp[3]);
    a0.x = fmaf(f0.x, w, a0.x); a0.y = fmaf(f0.y, w, a0.y);
    a0.z = fmaf(f1.x, w, a0.z); a0.w = fmaf(f1.y, w, a0.w);
    a1.x = fmaf(f2.x, w, a1.x); a1.y = fmaf(f2.y, w, a1.y);
    a1.z = fmaf(f3.x, w, a1.z); a1.w = fmaf(f3.y, w, a1.w);
}

__global__ __launch_bounds__(256)
void gather_kernel(const __half* __restrict__ hw16,
                   const float* __restrict__ dis, const float* __restrict__ b,
                   const int* __restrict__ start, const int* __restrict__ csr_src,
                   __half* __restrict__ hout16, float* __restrict__ meanOut, int n)
{
    __shared__ float ms[H];
    int warp = (blockIdx.x * blockDim.x + threadIdx.x) >> 5;
    int lane = threadIdx.x & 31;
    int node = warp;
    bool active = node < n;

    if (meanOut) {
        if (threadIdx.x < H) ms[threadIdx.x] = 0.0f;
        __syncthreads();
    }

    float4 a0 = make_float4(0, 0, 0, 0), a1 = make_float4(0, 0, 0, 0);

    if (active) {
        float dd = dis[node];
        float self = dd * dd;

        uint4 us = *reinterpret_cast<const uint4*>(hw16 + (size_t)node * H + lane * 8);
        const __half2* hs = reinterpret_cast<const __half2*>(&us);
        const float4* bb = reinterpret_cast<const float4*>(b);
        float4 b0 = bb[lane * 2 + 0];
        float4 b1 = bb[lane * 2 + 1];
        float2 s0 = __half22float2(hs[0]), s1 = __half22float2(hs[1]);
        float2 s2 = __half22float2(hs[2]), s3 = __half22float2(hs[3]);

        a0.x = fmaf(s0.x, self, b0.x); a0.y = fmaf(s0.y, self, b0.y);
        a0.z = fmaf(s1.x, self, b0.z); a0.w = fmaf(s1.y, self, b0.w);
        a1.x = fmaf(s2.x, self, b1.x); a1.y = fmaf(s2.y, self, b1.y);
        a1.z = fmaf(s3.x, self, b1.z); a1.w = fmaf(s3.y, self, b1.w);

        int j0 = start[node], j1 = start[node + 1];

        int j = j0;
        for (; j + 4 <= j1; j += 4) {
            int sA = csr_src[j], sB = csr_src[j + 1], sC = csr_src[j + 2], sD = csr_src[j + 3];
            float wA = dis[sA] * dd, wB = dis[sB] * dd, wC = dis[sC] * dd, wD = dis[sD] * dd;
            uint4 uA = *reinterpret_cast<const uint4*>(hw16 + (size_t)sA * H + lane * 8);
            uint4 uB = *reinterpret_cast<const uint4*>(hw16 + (size_t)sB * H + lane * 8);
            uint4 uC = *reinterpret_cast<const uint4*>(hw16 + (size_t)sC * H + lane * 8);
            uint4 uD = *reinterpret_cast<const uint4*>(hw16 + (size_t)sD * H + lane * 8);
            accum_row(reinterpret_cast<const __half2*>(&uA), wA, a0, a1);
            accum_row(reinterpret_cast<const __half2*>(&uB), wB, a0, a1);
            accum_row(reinterpret_cast<const __half2*>(&uC), wC, a0, a1);
            accum_row(reinterpret_cast<const __half2*>(&uD), wD, a0, a1);
        }
        for (; j < j1; ++j) {
            int s = csr_src[j];
            float w = dis[s] * dd;
            uint4 u = *reinterpret_cast<const uint4*>(hw16 + (size_t)s * H + lane * 8);
            accum_row(reinterpret_cast<const __half2*>(&u), w, a0, a1);
        }

        a0.x = fmaxf(a0.x, 0.f); a0.y = fmaxf(a0.y, 0.f);
        a0.z = fmaxf(a0.z, 0.f); a0.w = fmaxf(a0.w, 0.f);
        a1.x = fmaxf(a1.x, 0.f); a1.y = fmaxf(a1.y, 0.f);
        a1.z = fmaxf(a1.z, 0.f); a1.w = fmaxf(a1.w, 0.f);

        uint4 outw;
        __half2* ho = reinterpret_cast<__half2*>(&outw);
        ho[0] = __floats2half2_rn(a0.x, a0.y);
        ho[1] = __floats2half2_rn(a0.z, a0.w);
        ho[2] = __floats2half2_rn(a1.x, a1.y);
        ho[3] = __floats2half2_rn(a1.z, a1.w);
        *reinterpret_cast<uint4*>(hout16 + (size_t)node * H + lane * 8) = outw;
    }

    if (meanOut) {
        if (active) {
            // accumulate the STORED (fp16-rounded) values so mean matches h exactly
            int base = lane * 8;
            atomicAdd(&ms[base + 0], __half2float(__float2half_rn(a0.x)));
            atomicAdd(&ms[base + 1], __half2float(__float2half_rn(a0.y)));
            atomicAdd(&ms[base + 2], __half2float(__float2half_rn(a0.z)));
            atomicAdd(&ms[base + 3], __half2float(__float2half_rn(a0.w)));
            atomicAdd(&ms[base + 4], __half2float(__float2half_rn(a1.x)));
            atomicAdd(&ms[base + 5], __half2float(__float2half_rn(a1.y)));
            atomicAdd(&ms[base + 6], __half2float(__float2half_rn(a1.z)));
            atomicAdd(&ms[base + 7], __half2float(__float2half_rn(a1.w)));
        }
        __syncthreads();
        if (threadIdx.x < H) atomicAdd(&meanOut[threadIdx.x], ms[threadIdx.x]);
    }
}

// ---------------- head MLP ----------------
__global__ void head_kernel(const float* __restrict__ mean,
                            const float* __restrict__ W1, const float* __restrict__ b1,
                            const float* __restrict__ W2, const float* __restrict__ b2,
                            float* __restrict__ out, float invN)
{
    __shared__ float g[H];
    __shared__ float t[D_OUT];
    int tid = threadIdx.x;  // 128 threads
    g[tid]       = mean[tid]       * invN;
    g[tid + 128] = mean[tid + 128] * invN;
    __syncthreads();
    float acc = b1[tid];
    for (int k = 0; k < H; k++) acc = fmaf(g[k], W1[k * D_OUT + tid], acc);
    t[tid] = fmaxf(acc, 0.0f);
    __syncthreads();
    float acc2 = b2[tid];
    for (int k = 0; k < D_OUT; k++) acc2 = fmaf(t[k], W2[k * D_OUT + tid], acc2);
    out[tid] = acc2;
}

// ---------------- launch ----------------
extern "C" void kernel_launch(void* const* d_in, const int* in_sizes, int n_in,
                              void* d_out, int out_size)
{
    const float* x       = (const float*)d_in[0];
    const int*   eidx    = (const int*)  d_in[1];
    const float* W_enc1  = (const float*)d_in[3];
    const float* b_enc1  = (const float*)d_in[4];
    const float* W_enc2  = (const float*)d_in[5];
    const float* b_enc2  = (const float*)d_in[6];
    const float* W_g[3]  = { (const float*)d_in[8],  (const float*)d_in[10], (const float*)d_in[12] };
    const float* b_g[3]  = { (const float*)d_in[9],  (const float*)d_in[11], (const float*)d_in[13] };
    const float* W_h1    = (const float*)d_in[14];
    const float* b_h1    = (const float*)d_in[15];
    const float* W_h2    = (const float*)d_in[16];
    const float* b_h2    = (const float*)d_in[17];

    const int n = in_sizes[0] / D_IN;       // 50000
    const int E = in_sizes[2];              // 1600000
    const int* src = eidx;
    const int* dst = eidx + E;

    __half *p_x16, *p_h16, *p_hw16, *p_w16;
    float *p_dis, *p_mean;
    int *p_deg, *p_start, *p_cursor, *p_csr, *p_bsum, *p_boff;
    cudaGetSymbolAddress((void**)&p_x16,    g_x16);
    cudaGetSymbolAddress((void**)&p_h16,    g_h16);
    cudaGetSymbolAddress((void**)&p_hw16,   g_hw16);
    cudaGetSymbolAddress((void**)&p_w16,    g_w16);
    cudaGetSymbolAddress((void**)&p_dis,    g_dis);
    cudaGetSymbolAddress((void**)&p_deg,    g_deg);
    cudaGetSymbolAddress((void**)&p_start,  g_start);
    cudaGetSymbolAddress((void**)&p_cursor, g_cursor);
    cudaGetSymbolAddress((void**)&p_csr,    g_csr_src);
    cudaGetSymbolAddress((void**)&p_bsum,   g_bsum);
    cudaGetSymbolAddress((void**)&p_boff,   g_boff);
    cudaGetSymbolAddress((void**)&p_mean,   g_mean);

    __half* WT_enc1 = p_w16;                         // [H][D_INP]
    __half* WT_sq   = p_w16 + (size_t)H * D_INP;     // 4 x [H][H]

    // one-time stream/event infra (host objects only; no device memory)
    static cudaStream_t s2 = nullptr;
    static cudaEvent_t evFork = nullptr, evCsr = nullptr;
    if (!s2) {
        cudaStreamCreateWithFlags(&s2, cudaStreamNonBlocking);
        cudaEventCreateWithFlags(&evFork, cudaEventDisableTiming);
        cudaEventCreateWithFlags(&evCsr,  cudaEventDisableTiming);
    }

    // ---- fork: CSR chain on s2, encoder path on default stream ----
    cudaEventRecord(evFork, 0);
    cudaStreamWaitEvent(s2, evFork, 0);

    cudaMemsetAsync(p_deg, 0, n * sizeof(int), s2);
    deg_kernel<<<(E + 255) / 256, 256, 0, s2>>>(dst, p_deg, E);
    dis_kernel<<<(n + 255) / 256, 256, 0, s2>>>(p_deg, p_dis, n);
    const int nScanBlocks = (n + 1023) / 1024;
    scan_block_kernel<<<nScanBlocks, 1024, 0, s2>>>(p_deg, p_start, p_bsum, n);
    scan_sums_kernel<<<1, 64, 0, s2>>>(p_bsum, p_boff, nScanBlocks);
    scan_finalize_kernel<<<(n + 255) / 256, 256, 0, s2>>>(p_deg, p_start, p_boff, p_cursor, n);
    fill_csr_kernel<<<(E + 255) / 256, 256, 0, s2>>>(src, dst, p_cursor, p_csr, E);
    cudaEventRecord(evCsr, s2);

    // ---- default stream: conversions + encoder + first GCN GEMM ----
    wtrans_kernel<<<(H * D_INP + 255) / 256, 256>>>(W_enc1, WT_enc1, D_IN, H, D_INP);
    const float* wsrc[4] = { W_enc2, W_g[0], W_g[1], W_g[2] };
    for (int i = 0; i < 4; ++i)
        wtrans_kernel<<<(H * H + 255) / 256, 256>>>(wsrc[i], WT_sq + (size_t)i * H * H, H, H, H);
    xconv_kernel<<<(n * D_INP + 255) / 256, 256>>>(x, p_x16, n);
    cudaMemsetAsync(p_mean, 0, H * sizeof(float), 0);

    dim3 gemmBlock(256);
    dim3 gemmGrid(H / 128, (n + 127) / 128);

    fp16_gemm_kernel<<<gemmGrid, gemmBlock>>>(p_x16,  WT_enc1,           b_enc1, p_hw16, n, D_INP, H, 1);
    fp16_gemm_kernel<<<gemmGrid, gemmBlock>>>(p_hw16, WT_sq + 0 * H * H, b_enc2, p_h16,  n, H,     H, 0);
    fp16_gemm_kernel<<<gemmGrid, gemmBlock>>>(p_h16,  WT_sq + 1 * H * H, nullptr, p_hw16, n, H,    H, 0);

    // ---- join: gathers need the CSR ----
    cudaStreamWaitEvent(0, evCsr, 0);

    const int warpsPerBlock = 256 / 32;
    const int gatherBlocks = (n + warpsPerBlock - 1) / warpsPerBlock;

    gather_kernel<<<gatherBlocks, 256>>>(p_hw16, p_dis, b_g[0], p_start, p_csr, p_h16, nullptr, n);
    fp16_gemm_kernel<<<gemmGrid, gemmBlock>>>(p_h16, WT_sq + 2 * H * H, nullptr, p_hw16, n, H, H, 0);
    gather_kernel<<<gatherBlocks, 256>>>(p_hw16, p_dis, b_g[1], p_start, p_csr, p_h16, nullptr, n);
    fp16_gemm_kernel<<<gemmGrid, gemmBlock>>>(p_h16, WT_sq + 3 * H * H, nullptr, p_hw16, n, H, H, 0);
    // layer 3 gather fuses mean-pooling
    gather_kernel<<<gatherBlocks, 256>>>(p_hw16, p_dis, b_g[2], p_start, p_csr, p_h16, p_mean, n);

    head_kernel<<<1, D_OUT>>>(p_mean, W_h1, b_h1, W_h2, b_h2, (float*)d_out, 1.0f / (float)n);
}

// round 8
// speedup vs baseline: 8.7993x; 1.0369x over previous
#include <cuda_runtime.h>
#include <cuda_fp16.h>
#include <cuda_bf16.h>
#include <cstdint>

#define NODES_MAX 50000
#define EDGES_MAX 1600000
#define H 256
#define D_IN 518
#define D_INP 544
#define D_OUT 128

// ---------------- device scratch ----------------
__device__ __half g_h16  [NODES_MAX * H];
__device__ __half g_hwA  [NODES_MAX * H];
__device__ __half g_hwB  [NODES_MAX * H];
__device__ __half g_w16  [H * D_INP + 4 * H * H];
__device__ float  g_dis[NODES_MAX];
__device__ int    g_deg[NODES_MAX];
__device__ int    g_start[NODES_MAX + 1];
__device__ int    g_cursor[NODES_MAX];
__device__ int    g_csr_src[EDGES_MAX];
__device__ int    g_bsum[64];
__device__ int    g_boff[64];
__device__ float  g_mean[H];

// ---------------- weight transpose + fp16 ----------------
__global__ void wtrans_kernel(const float* __restrict__ W, __half* __restrict__ WT,
                              int K, int M, int Kp) {
    int idx = blockIdx.x * blockDim.x + threadIdx.x;
    if (idx >= M * Kp) return;
    int m = idx / Kp, k = idx % Kp;
    float v = (k < K) ? W[(size_t)k * M + m] : 0.0f;
    WT[idx] = __float2half_rn(v);
}

// ---------------- degree / normalization ----------------
__global__ void deg_kernel(const int* __restrict__ dst, int* __restrict__ deg, int E) {
    int i = blockIdx.x * blockDim.x + threadIdx.x;
    if (i < E) atomicAdd(&deg[dst[i]], 1);
}

__global__ void dis_kernel(const int* __restrict__ deg, float* __restrict__ dis, int n) {
    int i = blockIdx.x * blockDim.x + threadIdx.x;
    if (i < n) dis[i] = rsqrtf(1.0f + (float)deg[i]);
}

// ---------------- parallel scan (3 phases) ----------------
__global__ void scan_block_kernel(const int* __restrict__ deg, int* __restrict__ start,
                                  int* __restrict__ bsum, int n)
{
    __shared__ int warpSums[32];
    int i = blockIdx.x * 1024 + threadIdx.x;
    int lane = threadIdx.x & 31, warp = threadIdx.x >> 5;
    int v = (i < n) ? deg[i] : 0;
    int inc = v;
#pragma unroll
    for (int off = 1; off < 32; off <<= 1) {
        int t = __shfl_up_sync(0xffffffff, inc, off);
        if (lane >= off) inc += t;
    }
    if (lane == 31) warpSums[warp] = inc;
    __syncthreads();
    if (warp == 0) {
        int s = warpSums[lane];
#pragma unroll
        for (int off = 1; off < 32; off <<= 1) {
            int t = __shfl_up_sync(0xffffffff, s, off);
            if (lane >= off) s += t;
        }
        warpSums[lane] = s;
    }
    __syncthreads();
    int add = (warp > 0) ? warpSums[warp - 1] : 0;
    inc += add;
    if (i < n) start[i + 1] = inc;
    if (threadIdx.x == 1023) bsum[blockIdx.x] = inc;
}

__global__ void scan_sums_kernel(const int* __restrict__ bsum, int* __restrict__ boff, int nb) {
    int lane = threadIdx.x;
    int v = (lane < nb) ? bsum[lane] : 0;
    __shared__ int s[64];
    s[lane] = v;
    __syncthreads();
    for (int off = 1; off < 64; off <<= 1) {
        int t = (lane >= off) ? s[lane - off] : 0;
        __syncthreads();
        s[lane] += t;
        __syncthreads();
    }
    if (lane < nb) boff[lane] = (lane > 0) ? s[lane - 1] : 0;
}

__global__ void scan_finalize_kernel(const int* __restrict__ deg, int* __restrict__ start,
                                     const int* __restrict__ boff, int* __restrict__ cursor, int n)
{
    int i = blockIdx.x * blockDim.x + threadIdx.x;
    if (i < n) {
        int s = start[i + 1] + boff[i >> 10];
        start[i + 1] = s;
        cursor[i] = s - deg[i];
        if (i == 0) start[0] = 0;
    }
}

__global__ void fill_csr_kernel(const int* __restrict__ src, const int* __restrict__ dst,
                                int* __restrict__ cursor, int* __restrict__ csr_src, int E)
{
    int e = blockIdx.x * blockDim.x + threadIdx.x;
    if (e < E) {
        int d = dst[e];
        int p = atomicAdd(&cursor[d], 1);
        csr_src[p] = src[e];
    }
}

// ---------------- enc1: fp32-A x fp16-B GEMM (fused x conversion), BK=16 ----------------
// C16[N,M] = A32[N,K] @ BT16[M,Kp]^T (+bias)(+relu). Kp padded, zeros beyond K.
__global__ __launch_bounds__(256)
void enc1_gemm_kernel(const float* __restrict__ A, const __half* __restrict__ BT,
                      const float* __restrict__ bias, __half* __restrict__ C16,
                      int N, int K, int Kp, int M, int doRelu)
{
    const int BM = 128, BN = 128, BK = 16;
    const int PAD_M = 132;                 // fp32: stride 132 -> conflict-free fragments
    const int PAD_B = 24;                  // halves
    __shared__ float  As[2][BK][PAD_M];    // As[buf][k][m] fp32
    __shared__ alignas(16) __half Bh[2][BN][PAD_B];

    int tid = threadIdx.x;
    int wid = tid >> 5, lane = tid & 31;
    int warp_m = (wid & 1) * 64;
    int warp_n = (wid >> 1) * 32;
    int lq = lane & 3;
    int lg = lane >> 2;

    int row0 = blockIdx.y * BM;
    int col0 = blockIdx.x * BN;
    int nt = Kp / BK;

    float c[4][4][4];
#pragma unroll
    for (int mi = 0; mi < 4; mi++)
#pragma unroll
        for (int ni = 0; ni < 4; ni++)
#pragma unroll
            for (int r = 0; r < 4; r++) c[mi][ni][r] = 0.0f;

    int bRow = tid >> 1;                // 0..127
    int bCol = (tid & 1) * 8;           // halves

    auto loadTile = [&](int t, int buf) {
        int k0 = t * BK;
#pragma unroll
        for (int it = 0; it < 8; ++it) {
            int idx = it * 256 + tid;
            int m = idx >> 4, k = idx & 15;
            int gm = row0 + m, gk = k0 + k;
            const float* src = A + (size_t)gm * K + gk;
            uint32_t dsh = (uint32_t)__cvta_generic_to_shared(&As[buf][k][m]);
            int sz = (gm < N && gk < K) ? 4 : 0;
            asm volatile("cp.async.ca.shared.global [%0], [%1], 4, %2;"
                         :: "r"(dsh), "l"(src), "r"(sz));
        }
        {
            const __half* src = BT + (size_t)(col0 + bRow) * Kp + k0 + bCol;
            uint32_t dsh = (uint32_t)__cvta_generic_to_shared(&Bh[buf][bRow][bCol]);
            asm volatile("cp.async.cg.shared.global [%0], [%1], 16;"
                         :: "r"(dsh), "l"(src));
        }
        asm volatile("cp.async.commit_group;");
    };

    loadTile(0, 0);
    for (int t = 0; t < nt; ++t) {
        int buf = t & 1;
        if (t + 1 < nt) {
            loadTile(t + 1, (t + 1) & 1);
            asm volatile("cp.async.wait_group 1;");
        } else {
            asm volatile("cp.async.wait_group 0;");
        }
        __syncthreads();

        int kc = lq * 2;
        uint32_t af[4][4], bf[4][2];
#pragma unroll
        for (int mi = 0; mi < 4; mi++) {
            int mrow = warp_m + mi * 16 + lg;
            float a00 = As[buf][kc    ][mrow],     a01 = As[buf][kc + 1][mrow];
            float a10 = As[buf][kc    ][mrow + 8], a11 = As[buf][kc + 1][mrow + 8];
            float a20 = As[buf][kc + 8][mrow],     a21 = As[buf][kc + 9][mrow];
            float a30 = As[buf][kc + 8][mrow + 8], a31 = As[buf][kc + 9][mrow + 8];
            asm("cvt.rn.f16x2.f32 %0, %1, %2;" : "=r"(af[mi][0]) : "f"(a01), "f"(a00));
            asm("cvt.rn.f16x2.f32 %0, %1, %2;" : "=r"(af[mi][1]) : "f"(a11), "f"(a10));
            asm("cvt.rn.f16x2.f32 %0, %1, %2;" : "=r"(af[mi][2]) : "f"(a21), "f"(a20));
            asm("cvt.rn.f16x2.f32 %0, %1, %2;" : "=r"(af[mi][3]) : "f"(a31), "f"(a30));
        }
#pragma unroll
        for (int ni = 0; ni < 4; ni++) {
            int ncol = warp_n + ni * 8 + lg;
            bf[ni][0] = *reinterpret_cast<const uint32_t*>(&Bh[buf][ncol][kc    ]);
            bf[ni][1] = *reinterpret_cast<const uint32_t*>(&Bh[buf][ncol][kc + 8]);
        }
#pragma unroll
        for (int mi = 0; mi < 4; mi++)
#pragma unroll
            for (int ni = 0; ni < 4; ni++) {
                asm volatile(
                    "mma.sync.aligned.m16n8k16.row.col.f32.f16.f16.f32 "
                    "{%0,%1,%2,%3}, {%4,%5,%6,%7}, {%8,%9}, {%0,%1,%2,%3};"
                    : "+f"(c[mi][ni][0]), "+f"(c[mi][ni][1]),
                      "+f"(c[mi][ni][2]), "+f"(c[mi][ni][3])
                    : "r"(af[mi][0]), "r"(af[mi][1]), "r"(af[mi][2]), "r"(af[mi][3]),
                      "r"(bf[ni][0]), "r"(bf[ni][1]));
            }
        __syncthreads();
    }

#pragma unroll
    for (int mi = 0; mi < 4; mi++) {
#pragma unroll
        for (int ni = 0; ni < 4; ni++) {
            int r = row0 + warp_m + mi * 16 + lg;
            int cc = col0 + warp_n + ni * 8 + lq * 2;
            float v0 = c[mi][ni][0], v1 = c[mi][ni][1];
            float v2 = c[mi][ni][2], v3 = c[mi][ni][3];
            if (bias) {
                float bA = bias[cc], bB = bias[cc + 1];
                v0 += bA; v1 += bB; v2 += bA; v3 += bB;
            }
            if (doRelu) {
                v0 = fmaxf(v0, 0.f); v1 = fmaxf(v1, 0.f);
                v2 = fmaxf(v2, 0.f); v3 = fmaxf(v3, 0.f);
            }
            if (r < N)
                *reinterpret_cast<__half2*>(C16 + (size_t)r * M + cc) = __floats2half2_rn(v0, v1);
            if (r + 8 < N)
                *reinterpret_cast<__half2*>(C16 + (size_t)(r + 8) * M + cc) = __floats2half2_rn(v2, v3);
        }
    }
}

// ---------------- fp16 tensor-core GEMM, BK=32, cp.async double-buffered ----------------
__global__ __launch_bounds__(256)
void fp16_gemm_kernel(const __half* __restrict__ A, const __half* __restrict__ BT,
                      const float* __restrict__ bias, __half* __restrict__ C16,
                      int N, int K, int M, int doRelu)
{
    const int BM = 128, BN = 128, BK = 32, PAD = 40;
    __shared__ alignas(16) __half Ah[2][BM][PAD];
    __shared__ alignas(16) __half Bh[2][BN][PAD];

    int tid = threadIdx.x;
    int wid = tid >> 5, lane = tid & 31;
    int warp_m = (wid & 1) * 64;
    int warp_n = (wid >> 1) * 32;
    int lq = lane & 3;
    int lg = lane >> 2;

    int row0 = blockIdx.y * BM;
    int col0 = blockIdx.x * BN;
    int nt = K / BK;

    float c[4][4][4];
#pragma unroll
    for (int mi = 0; mi < 4; mi++)
#pragma unroll
        for (int ni = 0; ni < 4; ni++)
#pragma unroll
            for (int r = 0; r < 4; r++) c[mi][ni][r] = 0.0f;

    auto loadTile = [&](int t, int buf) {
        int k0 = t * BK;
#pragma unroll
        for (int it = 0; it < 2; ++it) {
            int chunk = it * 256 + tid;
            int r = chunk >> 2, c8 = (chunk & 3) * 8;
            {
                int gm = row0 + r;
                const __half* src = A + (size_t)gm * K + k0 + c8;
                uint32_t dsh = (uint32_t)__cvta_generic_to_shared(&Ah[buf][r][c8]);
                int sz = (gm < N) ? 16 : 0;
                asm volatile("cp.async.cg.shared.global [%0], [%1], 16, %2;"
                             :: "r"(dsh), "l"(src), "r"(sz));
            }
            {
                int gn = col0 + r;
                const __half* src = BT + (size_t)gn * K + k0 + c8;
                uint32_t dsh = (uint32_t)__cvta_generic_to_shared(&Bh[buf][r][c8]);
                asm volatile("cp.async.cg.shared.global [%0], [%1], 16;"
                             :: "r"(dsh), "l"(src));
            }
        }
        asm volatile("cp.async.commit_group;");
    };

    loadTile(0, 0);
    for (int t = 0; t < nt; ++t) {
        int buf = t & 1;
        if (t + 1 < nt) {
            loadTile(t + 1, (t + 1) & 1);
            asm volatile("cp.async.wait_group 1;");
        } else {
            asm volatile("cp.async.wait_group 0;");
        }
        __syncthreads();

#pragma unroll
        for (int kk = 0; kk < BK; kk += 16) {
            int kc = kk + lq * 2;
            uint32_t af[4][4], bf[4][2];
#pragma unroll
            for (int mi = 0; mi < 4; mi++) {
                int mrow = warp_m + mi * 16 + lg;
                af[mi][0] = *reinterpret_cast<const uint32_t*>(&Ah[buf][mrow    ][kc    ]);
                af[mi][1] = *reinterpret_cast<const uint32_t*>(&Ah[buf][mrow + 8][kc    ]);
                af[mi][2] = *reinterpret_cast<const uint32_t*>(&Ah[buf][mrow    ][kc + 8]);
                af[mi][3] = *reinterpret_cast<const uint32_t*>(&Ah[buf][mrow + 8][kc + 8]);
            }
#pragma unroll
            for (int ni = 0; ni < 4; ni++) {
                int ncol = warp_n + ni * 8 + lg;
                bf[ni][0] = *reinterpret_cast<const uint32_t*>(&Bh[buf][ncol][kc    ]);
                bf[ni][1] = *reinterpret_cast<const uint32_t*>(&Bh[buf][ncol][kc + 8]);
            }
#pragma unroll
            for (int mi = 0; mi < 4; mi++)
#pragma unroll
                for (int ni = 0; ni < 4; ni++) {
                    asm volatile(
                        "mma.sync.aligned.m16n8k16.row.col.f32.f16.f16.f32 "
                        "{%0,%1,%2,%3}, {%4,%5,%6,%7}, {%8,%9}, {%0,%1,%2,%3};"
                        : "+f"(c[mi][ni][0]), "+f"(c[mi][ni][1]),
                          "+f"(c[mi][ni][2]), "+f"(c[mi][ni][3])
                        : "r"(af[mi][0]), "r"(af[mi][1]), "r"(af[mi][2]), "r"(af[mi][3]),
                          "r"(bf[ni][0]), "r"(bf[ni][1]));
                }
        }
        __syncthreads();
    }

#pragma unroll
    for (int mi = 0; mi < 4; mi++) {
#pragma unroll
        for (int ni = 0; ni < 4; ni++) {
            int r = row0 + warp_m + mi * 16 + lg;
            int cc = col0 + warp_n + ni * 8 + lq * 2;
            float v0 = c[mi][ni][0], v1 = c[mi][ni][1];
            float v2 = c[mi][ni][2], v3 = c[mi][ni][3];
            if (bias) {
                float bA = bias[cc], bB = bias[cc + 1];
                v0 += bA; v1 += bB; v2 += bA; v3 += bB;
            }
            if (doRelu) {
                v0 = fmaxf(v0, 0.f); v1 = fmaxf(v1, 0.f);
                v2 = fmaxf(v2, 0.f); v3 = fmaxf(v3, 0.f);
            }
            if (r < N)
                *reinterpret_cast<__half2*>(C16 + (size_t)r * M + cc) = __floats2half2_rn(v0, v1);
            if (r + 8 < N)
                *reinterpret_cast<__half2*>(C16 + (size_t)(r + 8) * M + cc) = __floats2half2_rn(v2, v3);
        }
    }
}

// ---------------- fused GCN aggregation (+ optional mean), node-range version ----------------
__device__ __forceinline__ void accum_row(const __half2* hp, float w, float4& a0, float4& a1) {
    float2 f0 = __half22float2(hp[0]), f1 = __half22float2(hp[1]);
    float2 f2 = __half22float2(hp[2]), f3 = __half22float2(hp[3]);
    a0.x = fmaf(f0.x, w, a0.x); a0.y = fmaf(f0.y, w, a0.y);
    a0.z = fmaf(f1.x, w, a0.z); a0.w = fmaf(f1.y, w, a0.w);
    a1.x = fmaf(f2.x, w, a1.x); a1.y = fmaf(f2.y, w, a1.y);
    a1.z = fmaf(f3.x, w, a1.z); a1.w = fmaf(f3.y, w, a1.w);
}

__global__ __launch_bounds__(256)
void gather_kernel(const __half* __restrict__ hw16,
                   const float* __restrict__ dis, const float* __restrict__ b,
                   const int* __restrict__ start, const int* __restrict__ csr_src,
                   __half* __restrict__ hout16, float* __restrict__ meanOut,
                   int node0, int nNodes)
{
    __shared__ float ms[H];
    int warp = (blockIdx.x * blockDim.x + threadIdx.x) >> 5;
    int lane = threadIdx.x & 31;
    int node = node0 + warp;
    bool active = warp < nNodes;

    if (meanOut) {
        if (threadIdx.x < H) ms[threadIdx.x] = 0.0f;
        __syncthreads();
    }

    float4 a0 = make_float4(0, 0, 0, 0), a1 = make_float4(0, 0, 0, 0);

    if (active) {
        float dd = dis[node];
        float self = dd * dd;

        uint4 us = *reinterpret_cast<const uint4*>(hw16 + (size_t)node * H + lane * 8);
        const __half2* hs = reinterpret_cast<const __half2*>(&us);
        const float4* bb = reinterpret_cast<const float4*>(b);
        float4 b0 = bb[lane * 2 + 0];
        float4 b1 = bb[lane * 2 + 1];
        float2 s0 = __half22float2(hs[0]), s1 = __half22float2(hs[1]);
        float2 s2 = __half22float2(hs[2]), s3 = __half22float2(hs[3]);

        a0.x = fmaf(s0.x, self, b0.x); a0.y = fmaf(s0.y, self, b0.y);
        a0.z = fmaf(s1.x, self, b0.z); a0.w = fmaf(s1.y, self, b0.w);
        a1.x = fmaf(s2.x, self, b1.x); a1.y = fmaf(s2.y, self, b1.y);
        a1.z = fmaf(s3.x, self, b1.z); a1.w = fmaf(s3.y, self, b1.w);

        int j0 = start[node], j1 = start[node + 1];

        int j = j0;
        for (; j + 4 <= j1; j += 4) {
            int sA = csr_src[j], sB = csr_src[j + 1], sC = csr_src[j + 2], sD = csr_src[j + 3];
            float wA = dis[sA] * dd, wB = dis[sB] * dd, wC = dis[sC] * dd, wD = dis[sD] * dd;
            uint4 uA = *reinterpret_cast<const uint4*>(hw16 + (size_t)sA * H + lane * 8);
            uint4 uB = *reinterpret_cast<const uint4*>(hw16 + (size_t)sB * H + lane * 8);
            uint4 uC = *reinterpret_cast<const uint4*>(hw16 + (size_t)sC * H + lane * 8);
            uint4 uD = *reinterpret_cast<const uint4*>(hw16 + (size_t)sD * H + lane * 8);
            accum_row(reinterpret_cast<const __half2*>(&uA), wA, a0, a1);
            accum_row(reinterpret_cast<const __half2*>(&uB), wB, a0, a1);
            accum_row(reinterpret_cast<const __half2*>(&uC), wC, a0, a1);
            accum_row(reinterpret_cast<const __half2*>(&uD), wD, a0, a1);
        }
        for (; j < j1; ++j) {
            int s = csr_src[j];
            float w = dis[s] * dd;
            uint4 u = *reinterpret_cast<const uint4*>(hw16 + (size_t)s * H + lane * 8);
            accum_row(reinterpret_cast<const __half2*>(&u), w, a0, a1);
        }

        a0.x = fmaxf(a0.x, 0.f); a0.y = fmaxf(a0.y, 0.f);
        a0.z = fmaxf(a0.z, 0.f); a0.w = fmaxf(a0.w, 0.f);
        a1.x = fmaxf(a1.x, 0.f); a1.y = fmaxf(a1.y, 0.f);
        a1.z = fmaxf(a1.z, 0.f); a1.w = fmaxf(a1.w, 0.f);

        uint4 outw;
        __half2* ho = reinterpret_cast<__half2*>(&outw);
        ho[0] = __floats2half2_rn(a0.x, a0.y);
        ho[1] = __floats2half2_rn(a0.z, a0.w);
        ho[2] = __floats2half2_rn(a1.x, a1.y);
        ho[3] = __floats2half2_rn(a1.z, a1.w);
        *reinterpret_cast<uint4*>(hout16 + (size_t)node * H + lane * 8) = outw;
    }

    if (meanOut) {
        if (active) {
            int base = lane * 8;
            atomicAdd(&ms[base + 0], __half2float(__float2half_rn(a0.x)));
            atomicAdd(&ms[base + 1], __half2float(__float2half_rn(a0.y)));
            atomicAdd(&ms[base + 2], __half2float(__float2half_rn(a0.z)));
            atomicAdd(&ms[base + 3], __half2float(__float2half_rn(a0.w)));
            atomicAdd(&ms[base + 4], __half2float(__float2half_rn(a1.x)));
            atomicAdd(&ms[base + 5], __half2float(__float2half_rn(a1.y)));
            atomicAdd(&ms[base + 6], __half2float(__float2half_rn(a1.z)));
            atomicAdd(&ms[base + 7], __half2float(__float2half_rn(a1.w)));
        }
        __syncthreads();
        if (threadIdx.x < H) atomicAdd(&meanOut[threadIdx.x], ms[threadIdx.x]);
    }
}

// ---------------- head MLP ----------------
__global__ void head_kernel(const float* __restrict__ mean,
                            const float* __restrict__ W1, const float* __restrict__ b1,
                            const float* __restrict__ W2, const float* __restrict__ b2,
                            float* __restrict__ out, float invN)
{
    __shared__ float g[H];
    __shared__ float t[D_OUT];
    int tid = threadIdx.x;
    g[tid]       = mean[tid]       * invN;
    g[tid + 128] = mean[tid + 128] * invN;
    __syncthreads();
    float acc = b1[tid];
    for (int k = 0; k < H; k++) acc = fmaf(g[k], W1[k * D_OUT + tid], acc);
    t[tid] = fmaxf(acc, 0.0f);
    __syncthreads();
    float acc2 = b2[tid];
    for (int k = 0; k < D_OUT; k++) acc2 = fmaf(t[k], W2[k * D_OUT + tid], acc2);
    out[tid] = acc2;
}

// ---------------- launch ----------------
extern "C" void kernel_launch(void* const* d_in, const int* in_sizes, int n_in,
                              void* d_out, int out_size)
{
    const float* x       = (const float*)d_in[0];
    const int*   eidx    = (const int*)  d_in[1];
    const float* W_enc1  = (const float*)d_in[3];
    const float* b_enc1  = (const float*)d_in[4];
    const float* W_enc2  = (const float*)d_in[5];
    const float* b_enc2  = (const float*)d_in[6];
    const float* W_g[3]  = { (const float*)d_in[8],  (const float*)d_in[10], (const float*)d_in[12] };
    const float* b_g[3]  = { (const float*)d_in[9],  (const float*)d_in[11], (const float*)d_in[13] };
    const float* W_h1    = (const float*)d_in[14];
    const float* b_h1    = (const float*)d_in[15];
    const float* W_h2    = (const float*)d_in[16];
    const float* b_h2    = (const float*)d_in[17];

    const int n = in_sizes[0] / D_IN;       // 50000
    const int E = in_sizes[2];              // 1600000
    const int* src = eidx;
    const int* dst = eidx + E;

    __half *p_h16, *p_hwA, *p_hwB, *p_w16;
    float *p_dis, *p_mean;
    int *p_deg, *p_start, *p_cursor, *p_csr, *p_bsum, *p_boff;
    cudaGetSymbolAddress((void**)&p_h16,    g_h16);
    cudaGetSymbolAddress((void**)&p_hwA,    g_hwA);
    cudaGetSymbolAddress((void**)&p_hwB,    g_hwB);
    cudaGetSymbolAddress((void**)&p_w16,    g_w16);
    cudaGetSymbolAddress((void**)&p_dis,    g_dis);
    cudaGetSymbolAddress((void**)&p_deg,    g_deg);
    cudaGetSymbolAddress((void**)&p_start,  g_start);
    cudaGetSymbolAddress((void**)&p_cursor, g_cursor);
    cudaGetSymbolAddress((void**)&p_csr,    g_csr_src);
    cudaGetSymbolAddress((void**)&p_bsum,   g_bsum);
    cudaGetSymbolAddress((void**)&p_boff,   g_boff);
    cudaGetSymbolAddress((void**)&p_mean,   g_mean);

    __half* WT_enc1 = p_w16;                         // [H][D_INP]
    __half* WT_sq   = p_w16 + (size_t)H * D_INP;     // 4 x [H][H]

    static cudaStream_t s2 = nullptr, s3 = nullptr;
    static cudaEvent_t evFork = nullptr, evCsr = nullptr, evW = nullptr;
    static cudaEvent_t evG1a = nullptr, evM2a = nullptr, evG2a = nullptr, evM3a = nullptr;
    if (!s2) {
        cudaStreamCreateWithFlags(&s2, cudaStreamNonBlocking);
        cudaStreamCreateWithFlags(&s3, cudaStreamNonBlocking);
        cudaEventCreateWithFlags(&evFork, cudaEventDisableTiming);
        cudaEventCreateWithFlags(&evCsr,  cudaEventDisableTiming);
        cudaEventCreateWithFlags(&evW,    cudaEventDisableTiming);
        cudaEventCreateWithFlags(&evG1a,  cudaEventDisableTiming);
        cudaEventCreateWithFlags(&evM2a,  cudaEventDisableTiming);
        cudaEventCreateWithFlags(&evG2a,  cudaEventDisableTiming);
        cudaEventCreateWithFlags(&evM3a,  cudaEventDisableTiming);
    }

    // ---- fork ----
    cudaEventRecord(evFork, 0);
    cudaStreamWaitEvent(s2, evFork, 0);
    cudaStreamWaitEvent(s3, evFork, 0);

    // s2: CSR chain
    cudaMemsetAsync(p_deg, 0, n * sizeof(int), s2);
    deg_kernel<<<(E + 255) / 256, 256, 0, s2>>>(dst, p_deg, E);
    dis_kernel<<<(n + 255) / 256, 256, 0, s2>>>(p_deg, p_dis, n);
    const int nScanBlocks = (n + 1023) / 1024;
    scan_block_kernel<<<nScanBlocks, 1024, 0, s2>>>(p_deg, p_start, p_bsum, n);
    scan_sums_kernel<<<1, 64, 0, s2>>>(p_bsum, p_boff, nScanBlocks);
    scan_finalize_kernel<<<(n + 255) / 256, 256, 0, s2>>>(p_deg, p_start, p_boff, p_cursor, n);
    fill_csr_kernel<<<(E + 255) / 256, 256, 0, s2>>>(src, dst, p_cursor, p_csr, E);
    cudaEventRecord(evCsr, s2);

    // s3: weight conversions
    wtrans_kernel<<<(H * D_INP + 255) / 256, 256, 0, s3>>>(W_enc1, WT_enc1, D_IN, H, D_INP);
    const float* wsrc[4] = { W_enc2, W_g[0], W_g[1], W_g[2] };
    for (int i = 0; i < 4; ++i)
        wtrans_kernel<<<(H * H + 255) / 256, 256, 0, s3>>>(wsrc[i], WT_sq + (size_t)i * H * H, H, H, H);
    cudaEventRecord(evW, s3);

    // s0: mean clear + encoder chain
    cudaMemsetAsync(p_mean, 0, H * sizeof(float), 0);
    cudaStreamWaitEvent(0, evW, 0);

    dim3 gemmBlock(256);
    dim3 gemmGridFull(H / 128, (n + 127) / 128);

    enc1_gemm_kernel<<<gemmGridFull, gemmBlock>>>(x, WT_enc1, b_enc1, p_hwA, n, D_IN, D_INP, H, 1);
    fp16_gemm_kernel<<<gemmGridFull, gemmBlock>>>(p_hwA, WT_sq + 0 * H * H, b_enc2, p_h16, n, H, H, 0);
    fp16_gemm_kernel<<<gemmGridFull, gemmBlock>>>(p_h16, WT_sq + 1 * H * H, nullptr, p_hwA, n, H, H, 0);

    // ---- join CSR, then split-pipelined GCN layers ----
    cudaStreamWaitEvent(0, evCsr, 0);

    const int n2 = 25088;                 // 128-aligned split
    const int rowsB = n - n2;             // 24912
    dim3 gridHalfA(H / 128, n2 / 128);                    // 196
    dim3 gridHalfB(H / 128, (rowsB + 127) / 128);         // 195
    const int gBlocksA = (n2 + 7) / 8;
    const int gBlocksB = (rowsB + 7) / 8;
    const int gBlocksFull = (n + 7) / 8;

    // layer 1: gather from hwA -> h16 (split); GEMM g2 -> hwB
    gather_kernel<<<gBlocksA, 256>>>(p_hwA, p_dis, b_g[0], p_start, p_csr, p_h16, nullptr, 0, n2);
    cudaEventRecord(evG1a, 0);
    cudaStreamWaitEvent(s2, evG1a, 0);
    fp16_gemm_kernel<<<gridHalfA, gemmBlock, 0, s2>>>(p_h16, WT_sq + 2 * H * H, nullptr, p_hwB, n2, H, H, 0);
    cudaEventRecord(evM2a, s2);
    gather_kernel<<<gBlocksB, 256>>>(p_hwA, p_dis, b_g[0], p_start, p_csr, p_h16, nullptr, n2, rowsB);
    fp16_gemm_kernel<<<gridHalfB, gemmBlock>>>(p_h16 + (size_t)n2 * H, WT_sq + 2 * H * H, nullptr,
                                               p_hwB + (size_t)n2 * H, rowsB, H, H, 0);
    cudaStreamWaitEvent(0, evM2a, 0);

    // layer 2: gather from hwB -> h16 (split); GEMM g3 -> hwA
    gather_kernel<<<gBlocksA, 256>>>(p_hwB, p_dis, b_g[1], p_start, p_csr, p_h16, nullptr, 0, n2);
    cudaEventRecord(evG2a, 0);
    cudaStreamWaitEvent(s2, evG2a, 0);
    fp16_gemm_kernel<<<gridHalfA, gemmBlock, 0, s2>>>(p_h16, WT_sq + 3 * H * H, nullptr, p_hwA, n2, H, H, 0);
    cudaEventRecord(evM3a, s2);
    gather_kernel<<<gBlocksB, 256>>>(p_hwB, p_dis, b_g[1], p_start, p_csr, p_h16, nullptr, n2, rowsB);
    fp16_gemm_kernel<<<gridHalfB, gemmBlock>>>(p_h16 + (size_t)n2 * H, WT_sq + 3 * H * H, nullptr,
                                               p_hwA + (size_t)n2 * H, rowsB, H, H, 0);
    cudaStreamWaitEvent(0, evM3a, 0);

    // layer 3: full gather from hwA (+fused mean)
    gather_kernel<<<gBlocksFull, 256>>>(p_hwA, p_dis, b_g[2], p_start, p_csr, p_h16, p_mean, 0, n);

    head_kernel<<<1, D_OUT>>>(p_mean, W_h1, b_h1, W_h2, b_h2, (float*)d_out, 1.0f / (float)n);
}